// round 2
// baseline (speedup 1.0000x reference)
#include <cuda_runtime.h>
#include <math.h>

// Problem constants
#define CB   8
#define CS   1024
#define CD   1024
#define CH   16
#define CDK  64
#define CDFF 4096

// ---------------------------------------------------------------------------
// Scratch (device globals: allocation-free per harness rules)
// ---------------------------------------------------------------------------
__device__ float g_xn[CB * CS * CD];                 // 32 MB  LN output
__device__ float g_q [CB * CS * CD];                 // 32 MB  [B,S,H,DK]
__device__ float g_k [CB * CS * CD];                 // 32 MB
__device__ float g_v [CB * CS * CD];                 // 32 MB
__device__ float g_o [CB * CS * CD];                 // 32 MB  attn out [B,S,D]
__device__ float g_h1[(size_t)CB * CS * CDFF];       // 128 MB FFN hidden
__device__ float g_sc[(size_t)CB * CH * CS * CS];    // 512 MB scores/probs

// ---------------------------------------------------------------------------
// LayerNorm: matches jnp.std(ddof=1), eps added to std (not var)
// one block of 256 threads per row of 1024
// ---------------------------------------------------------------------------
__global__ __launch_bounds__(256)
void ln_kernel(const float* __restrict__ x,
               const float* __restrict__ gamma,
               const float* __restrict__ beta,
               float* __restrict__ out)
{
    const int row = blockIdx.x;
    const float* xr = x + (size_t)row * CD;
    float* orow = out + (size_t)row * CD;
    const int t = threadIdx.x;

    float v[4];
#pragma unroll
    for (int i = 0; i < 4; i++) v[i] = xr[t + 256 * i];

    __shared__ float red[8];
    __shared__ float s_mean, s_rstd;

    // mean
    float s = v[0] + v[1] + v[2] + v[3];
#pragma unroll
    for (int o = 16; o > 0; o >>= 1) s += __shfl_xor_sync(0xffffffffu, s, o);
    if ((t & 31) == 0) red[t >> 5] = s;
    __syncthreads();
    if (t < 8) {
        float r = red[t];
#pragma unroll
        for (int o = 4; o > 0; o >>= 1) r += __shfl_xor_sync(0xffu, r, o);
        if (t == 0) s_mean = r * (1.0f / CD);
    }
    __syncthreads();
    const float mean = s_mean;

    // unbiased variance
    float q = 0.f;
#pragma unroll
    for (int i = 0; i < 4; i++) { float d = v[i] - mean; q += d * d; }
#pragma unroll
    for (int o = 16; o > 0; o >>= 1) q += __shfl_xor_sync(0xffffffffu, q, o);
    if ((t & 31) == 0) red[t >> 5] = q;
    __syncthreads();
    if (t < 8) {
        float r = red[t];
#pragma unroll
        for (int o = 4; o > 0; o >>= 1) r += __shfl_xor_sync(0xffu, r, o);
        if (t == 0) s_rstd = 1.0f / (sqrtf(r * (1.0f / (CD - 1))) + 1e-5f);
    }
    __syncthreads();
    const float rstd = s_rstd;

#pragma unroll
    for (int i = 0; i < 4; i++) {
        int c = t + 256 * i;
        orow[c] = gamma[c] * (v[i] - mean) * rstd + beta[c];
    }
}

// ---------------------------------------------------------------------------
// Masked softmax over score rows (in-place). 1 block / row, row = 1024.
// ---------------------------------------------------------------------------
__global__ __launch_bounds__(256)
void softmax_kernel(float* __restrict__ scores, const int* __restrict__ mask)
{
    const long row = blockIdx.x;          // (b, h, q) flattened: B*H*S rows
    const int  b   = (int)(row / ((long)CH * CS));
    const int  qi  = (int)(row % CS);
    float* sr = scores + row * (long)CS;
    const int* mr = mask + ((size_t)b * CS + qi) * CS;
    const int t = threadIdx.x;

    __shared__ float red[8];
    __shared__ float s_max, s_inv;

    float v[4];
    float mx = -INFINITY;
#pragma unroll
    for (int i = 0; i < 4; i++) {
        int c = t + 256 * i;
        float s = (mr[c] == 0) ? -1e9f : sr[c];
        v[i] = s;
        mx = fmaxf(mx, s);
    }
#pragma unroll
    for (int o = 16; o > 0; o >>= 1) mx = fmaxf(mx, __shfl_xor_sync(0xffffffffu, mx, o));
    if ((t & 31) == 0) red[t >> 5] = mx;
    __syncthreads();
    if (t < 8) {
        float r = red[t];
#pragma unroll
        for (int o = 4; o > 0; o >>= 1) r = fmaxf(r, __shfl_xor_sync(0xffu, r, o));
        if (t == 0) s_max = r;
    }
    __syncthreads();
    const float m = s_max;

    float sum = 0.f;
#pragma unroll
    for (int i = 0; i < 4; i++) { v[i] = expf(v[i] - m); sum += v[i]; }
#pragma unroll
    for (int o = 16; o > 0; o >>= 1) sum += __shfl_xor_sync(0xffffffffu, sum, o);
    if ((t & 31) == 0) red[t >> 5] = sum;
    __syncthreads();
    if (t < 8) {
        float r = red[t];
#pragma unroll
        for (int o = 4; o > 0; o >>= 1) r += __shfl_xor_sync(0xffu, r, o);
        if (t == 0) s_inv = 1.0f / r;
    }
    __syncthreads();
    const float inv = s_inv;
#pragma unroll
    for (int i = 0; i < 4; i++) sr[t + 256 * i] = v[i] * inv;
}

// ---------------------------------------------------------------------------
// Tiled fp32 GEMM.
//   TRANSB=true : C[m,n] = alpha * sum_k A[m,k] * B[n,k]     (B row-major [N,K])
//   TRANSB=false: C[m,n] = alpha * sum_k A[m,k] * B[k,n]     (B row-major [K,N])
// Batched via blockIdx.z: offset = (z/HH)*s_outer + (z%HH)*s_inner per operand.
// Epilogue: +bias[n] (optional), GELU (compile-time), +res (optional, C-indexed).
// Assumes all dims multiples of tile sizes (true for every call here).
// ---------------------------------------------------------------------------
__device__ __forceinline__ float gelu_f(float x)
{
    const float c = 0.7978845608028654f; // sqrt(2/pi)
    float x3 = x * x * x;
    return 0.5f * x * (1.0f + tanhf(c * (x + 0.044715f * x3)));
}

template <int BM, int BN, int BK, int TM, int TN, bool TRANSB, bool GELU>
__global__ __launch_bounds__((BM / TM) * (BN / TN))
void gemm_kernel(const float* __restrict__ A, int lda, long sAo, long sAi,
                 const float* __restrict__ Bm, int ldb, long sBo, long sBi,
                 float* __restrict__ C, int ldc, long sCo, long sCi,
                 const float* __restrict__ bias,
                 const float* __restrict__ res,
                 float alpha, int K, int HH)
{
    constexpr int THREADS = (BM / TM) * (BN / TN);
    const int z  = blockIdx.z;
    const int zo = z / HH, zi = z % HH;
    A  += (size_t)zo * sAo + (size_t)zi * sAi;
    Bm += (size_t)zo * sBo + (size_t)zi * sBi;
    const size_t cOff = (size_t)zo * sCo + (size_t)zi * sCi;
    C += cOff;
    if (res) res += cOff;

    __shared__ float As[BK][BM];
    __shared__ float Bs[BK][BN];

    const int bm = blockIdx.y * BM;
    const int bn = blockIdx.x * BN;
    const int tid = threadIdx.x;
    const int tx = tid % (BN / TN);
    const int ty = tid / (BN / TN);

    float acc[TM][TN];
#pragma unroll
    for (int i = 0; i < TM; i++)
#pragma unroll
        for (int j = 0; j < TN; j++) acc[i][j] = 0.f;

    for (int k0 = 0; k0 < K; k0 += BK) {
        // A tile [BM x BK] -> As[k][m]
        constexpr int LA = BM * BK / (4 * THREADS);
#pragma unroll
        for (int i = 0; i < LA; i++) {
            int idx = tid + i * THREADS;          // float4 id
            int r   = idx / (BK / 4);
            int c4  = idx % (BK / 4);
            float4 a = *reinterpret_cast<const float4*>(
                A + (size_t)(bm + r) * lda + k0 + c4 * 4);
            As[c4 * 4 + 0][r] = a.x;
            As[c4 * 4 + 1][r] = a.y;
            As[c4 * 4 + 2][r] = a.z;
            As[c4 * 4 + 3][r] = a.w;
        }
        if (TRANSB) {
            // B tile [BN x BK] -> Bs[k][n]
            constexpr int LB = BN * BK / (4 * THREADS);
#pragma unroll
            for (int i = 0; i < LB; i++) {
                int idx = tid + i * THREADS;
                int r   = idx / (BK / 4);
                int c4  = idx % (BK / 4);
                float4 b = *reinterpret_cast<const float4*>(
                    Bm + (size_t)(bn + r) * ldb + k0 + c4 * 4);
                Bs[c4 * 4 + 0][r] = b.x;
                Bs[c4 * 4 + 1][r] = b.y;
                Bs[c4 * 4 + 2][r] = b.z;
                Bs[c4 * 4 + 3][r] = b.w;
            }
        } else {
            // B tile [BK x BN] -> Bs[k][n], already n-contiguous
            constexpr int LB = BK * BN / (4 * THREADS);
#pragma unroll
            for (int i = 0; i < LB; i++) {
                int idx = tid + i * THREADS;
                int r   = idx / (BN / 4);
                int c4  = idx % (BN / 4);
                *reinterpret_cast<float4*>(&Bs[r][c4 * 4]) =
                    *reinterpret_cast<const float4*>(
                        Bm + (size_t)(k0 + r) * ldb + bn + c4 * 4);
            }
        }
        __syncthreads();

#pragma unroll
        for (int k = 0; k < BK; k++) {
            float a[TM], b[TN];
#pragma unroll
            for (int i = 0; i < TM; i++) a[i] = As[k][ty * TM + i];
#pragma unroll
            for (int j = 0; j < TN; j++) b[j] = Bs[k][tx * TN + j];
#pragma unroll
            for (int i = 0; i < TM; i++)
#pragma unroll
                for (int j = 0; j < TN; j++)
                    acc[i][j] = fmaf(a[i], b[j], acc[i][j]);
        }
        __syncthreads();
    }

    // Epilogue: alpha -> +bias -> GELU -> +residual
#pragma unroll
    for (int i = 0; i < TM; i++) {
        int m = bm + ty * TM + i;
#pragma unroll
        for (int j = 0; j < TN; j++) {
            int n = bn + tx * TN + j;
            float v = acc[i][j] * alpha;
            if (bias) v += bias[n];
            if (GELU) v = gelu_f(v);
            if (res)  v += res[(size_t)m * ldc + n];
            C[(size_t)m * ldc + n] = v;
        }
    }
}

// ---------------------------------------------------------------------------
// Launch
// ---------------------------------------------------------------------------
extern "C" void kernel_launch(void* const* d_in, const int* in_sizes, int n_in,
                              void* d_out, int out_size)
{
    const float* x    = (const float*)d_in[0];
    const int*   mask = (const int*)  d_in[1];
    const float* wq   = (const float*)d_in[2];
    const float* bq   = (const float*)d_in[3];
    const float* wk   = (const float*)d_in[4];
    const float* bk   = (const float*)d_in[5];
    const float* wv   = (const float*)d_in[6];
    const float* bv   = (const float*)d_in[7];
    const float* wo   = (const float*)d_in[8];
    const float* bo   = (const float*)d_in[9];
    const float* w1   = (const float*)d_in[10];
    const float* b1   = (const float*)d_in[11];
    const float* w2   = (const float*)d_in[12];
    const float* b2   = (const float*)d_in[13];
    const float* g1   = (const float*)d_in[14];
    const float* be1  = (const float*)d_in[15];
    const float* g2   = (const float*)d_in[16];
    const float* be2  = (const float*)d_in[17];
    float* out = (float*)d_out;

    float *xn, *q, *k, *v, *o, *h1, *sc;
    cudaGetSymbolAddress((void**)&xn, g_xn);
    cudaGetSymbolAddress((void**)&q,  g_q);
    cudaGetSymbolAddress((void**)&k,  g_k);
    cudaGetSymbolAddress((void**)&v,  g_v);
    cudaGetSymbolAddress((void**)&o,  g_o);
    cudaGetSymbolAddress((void**)&h1, g_h1);
    cudaGetSymbolAddress((void**)&sc, g_sc);

    const int M = CB * CS;  // 8192 token rows

    // 1) LN1
    ln_kernel<<<M, 256>>>(x, g1, be1, xn);

    // 2-4) Q,K,V = xn @ W^T + b, kept in [B,S,H,DK] (== [M,D] row-major)
    dim3 gD(CD / 128, M / 128, 1);
    gemm_kernel<128,128,16,8,8,true,false><<<gD, 256>>>(
        xn, CD, 0, 0,  wq, CD, 0, 0,  q, CD, 0, 0,  bq, nullptr, 1.0f, CD, 1);
    gemm_kernel<128,128,16,8,8,true,false><<<gD, 256>>>(
        xn, CD, 0, 0,  wk, CD, 0, 0,  k, CD, 0, 0,  bk, nullptr, 1.0f, CD, 1);
    gemm_kernel<128,128,16,8,8,true,false><<<gD, 256>>>(
        xn, CD, 0, 0,  wv, CD, 0, 0,  v, CD, 0, 0,  bv, nullptr, 1.0f, CD, 1);

    // 5) scores[z] = (1/8) * Q_z @ K_z^T, z over (b,h); operand base = b*S*D + h*DK
    dim3 gS(CS / 128, CS / 128, CB * CH);
    gemm_kernel<128,128,16,8,8,true,false><<<gS, 256>>>(
        q,  CD, (long)CS * CD, CDK,
        k,  CD, (long)CS * CD, CDK,
        sc, CS, (long)CH * CS * CS, (long)CS * CS,
        nullptr, nullptr, 0.125f, CDK, CH);

    // 6) masked softmax in place
    softmax_kernel<<<CB * CH * CS, 256>>>(sc, mask);

    // 7) O_z = P_z @ V_z  (B non-transposed), written straight into [B,S,D]
    dim3 gP(CDK / 64, CS / 128, CB * CH);
    gemm_kernel<128,64,16,8,4,false,false><<<gP, 256>>>(
        sc, CS, (long)CH * CS * CS, (long)CS * CS,
        v,  CD, (long)CS * CD, CDK,
        o,  CD, (long)CS * CD, CDK,
        nullptr, nullptr, 1.0f, CS, CH);

    // 8) x1 = o @ wo^T + bo + x   -> out
    gemm_kernel<128,128,16,8,8,true,false><<<gD, 256>>>(
        o, CD, 0, 0,  wo, CD, 0, 0,  out, CD, 0, 0,  bo, x, 1.0f, CD, 1);

    // 9) LN2
    ln_kernel<<<M, 256>>>(out, g2, be2, xn);

    // 10) h1 = gelu(xn @ w1^T + b1)
    dim3 gF1(CDFF / 128, M / 128, 1);
    gemm_kernel<128,128,16,8,8,true,true><<<gF1, 256>>>(
        xn, CD, 0, 0,  w1, CD, 0, 0,  h1, CDFF, 0, 0,  b1, nullptr, 1.0f, CD, 1);

    // 11) out = x1 + h1 @ w2^T + b2
    gemm_kernel<128,128,16,8,8,true,false><<<gD, 256>>>(
        h1, CDFF, 0, 0,  w2, CDFF, 0, 0,  out, CD, 0, 0,  b2, out, 1.0f, CDFF, 1);
}

// round 4
// speedup vs baseline: 2.8310x; 2.8310x over previous
#include <cuda_runtime.h>
#include <cuda_bf16.h>
#include <math.h>
#include <stdint.h>

#define CB 8
#define CS 1024
#define CD 1024
#define CH 16
#define CDK 64
#define CDFF 4096
#define NTOK (CB*CS)
typedef __nv_bfloat16 bf16;

#define SWZ(o) ((o) ^ (((o) >> 3) & 0x70))
#define CP16(dst, src) asm volatile("cp.async.cg.shared.global [%0], [%1], 16;" :: "r"(dst), "l"(src) : "memory")

#define LDSM4(r, a) \
    asm volatile("ldmatrix.sync.aligned.m8n8.x4.shared.b16 {%0,%1,%2,%3}, [%4];" \
        : "=r"((r)[0]), "=r"((r)[1]), "=r"((r)[2]), "=r"((r)[3]) : "r"(a))

#define MMA(c, a, b) \
    asm volatile("mma.sync.aligned.m16n8k16.row.col.f32.bf16.bf16.f32 " \
        "{%0,%1,%2,%3},{%4,%5,%6,%7},{%8,%9},{%0,%1,%2,%3};" \
        : "+f"((c)[0]), "+f"((c)[1]), "+f"((c)[2]), "+f"((c)[3]) \
        : "r"((a)[0]), "r"((a)[1]), "r"((a)[2]), "r"((a)[3]), "r"((b)[0]), "r"((b)[1]))

__device__ __forceinline__ float gelu_f(float x) {
    float x3 = x * x * x;
    return 0.5f * x * (1.0f + tanhf(0.7978845608028654f * (x + 0.044715f * x3)));
}
__device__ __forceinline__ void split_store(float v, bf16* h, bf16* l, size_t i) {
    bf16 hi = __float2bfloat16(v);
    h[i] = hi;
    l[i] = __float2bfloat16(v - __bfloat162float(hi));
}

// ------------------------- scratch -------------------------
__device__ bf16 g_xnh[NTOK*CD], g_xnl[NTOK*CD];
__device__ bf16 g_qh[NTOK*CD],  g_ql[NTOK*CD];
__device__ bf16 g_kh[NTOK*CD],  g_kl[NTOK*CD];
__device__ bf16 g_vth[NTOK*CD], g_vtl[NTOK*CD];           // V^T [B,H,DK,S]
__device__ bf16 g_oh[NTOK*CD],  g_ol[NTOK*CD];
__device__ bf16 g_h1h[(size_t)NTOK*CDFF], g_h1l[(size_t)NTOK*CDFF];
__device__ float g_sc[(size_t)CB*CH*CS*CS];
__device__ bf16 g_ph[(size_t)CB*CH*CS*CS], g_pl[(size_t)CB*CH*CS*CS];
__device__ bf16 g_wqh[CD*CD], g_wql[CD*CD], g_wkh[CD*CD], g_wkl[CD*CD];
__device__ bf16 g_wvh[CD*CD], g_wvl[CD*CD], g_woh[CD*CD], g_wol[CD*CD];
__device__ bf16 g_w1h[(size_t)CDFF*CD], g_w1l[(size_t)CDFF*CD];
__device__ bf16 g_w2h[(size_t)CD*CDFF], g_w2l[(size_t)CD*CDFF];

__global__ __launch_bounds__(256)
void split_kernel(const float* __restrict__ w, bf16* __restrict__ h, bf16* __restrict__ l, int n) {
    int i = blockIdx.x * 256 + threadIdx.x;
    if (i < n) split_store(w[i], h, l, (size_t)i);
}

// ------------------------- LayerNorm (ddof=1, eps on std) -> split -------------------------
__global__ __launch_bounds__(256)
void ln_split_kernel(const float* __restrict__ x, const float* __restrict__ gamma,
                     const float* __restrict__ beta, bf16* __restrict__ oh, bf16* __restrict__ ol) {
    const int row = blockIdx.x;
    const float* xr = x + (size_t)row * CD;
    const int t = threadIdx.x;
    float v[4];
#pragma unroll
    for (int i = 0; i < 4; i++) v[i] = xr[t + 256 * i];
    __shared__ float red[8];
    __shared__ float s_mean, s_rstd;
    float s = v[0] + v[1] + v[2] + v[3];
#pragma unroll
    for (int o = 16; o > 0; o >>= 1) s += __shfl_xor_sync(~0u, s, o);
    if ((t & 31) == 0) red[t >> 5] = s;
    __syncthreads();
    if (t < 8) {
        float r = red[t];
#pragma unroll
        for (int o = 4; o > 0; o >>= 1) r += __shfl_xor_sync(0xffu, r, o);
        if (t == 0) s_mean = r * (1.0f / CD);
    }
    __syncthreads();
    const float mean = s_mean;
    float q = 0.f;
#pragma unroll
    for (int i = 0; i < 4; i++) { float d = v[i] - mean; q += d * d; }
#pragma unroll
    for (int o = 16; o > 0; o >>= 1) q += __shfl_xor_sync(~0u, q, o);
    if ((t & 31) == 0) red[t >> 5] = q;
    __syncthreads();
    if (t < 8) {
        float r = red[t];
#pragma unroll
        for (int o = 4; o > 0; o >>= 1) r += __shfl_xor_sync(0xffu, r, o);
        if (t == 0) s_rstd = 1.0f / (sqrtf(r * (1.0f / (CD - 1))) + 1e-5f);
    }
    __syncthreads();
    const float rstd = s_rstd;
#pragma unroll
    for (int i = 0; i < 4; i++) {
        int c = t + 256 * i;
        split_store(gamma[c] * (v[i] - mean) * rstd + beta[c], oh, ol, (size_t)row * CD + c);
    }
}

// ------------------------- masked softmax -> split probs -------------------------
__global__ __launch_bounds__(256)
void softmax_split_kernel(const float* __restrict__ scores, const int* __restrict__ mask,
                          bf16* __restrict__ ph, bf16* __restrict__ pl) {
    const long row = blockIdx.x;
    const int b = (int)(row / ((long)CH * CS));
    const int qi = (int)(row % CS);
    const float* sr = scores + row * (long)CS;
    const int* mr = mask + ((size_t)b * CS + qi) * CS;
    const int t = threadIdx.x;
    __shared__ float red[8];
    __shared__ float s_max, s_inv;
    float v[4];
    float mx = -INFINITY;
#pragma unroll
    for (int i = 0; i < 4; i++) {
        int c = t + 256 * i;
        float s = (mr[c] == 0) ? -1e9f : sr[c];
        v[i] = s;
        mx = fmaxf(mx, s);
    }
#pragma unroll
    for (int o = 16; o > 0; o >>= 1) mx = fmaxf(mx, __shfl_xor_sync(~0u, mx, o));
    if ((t & 31) == 0) red[t >> 5] = mx;
    __syncthreads();
    if (t < 8) {
        float r = red[t];
#pragma unroll
        for (int o = 4; o > 0; o >>= 1) r = fmaxf(r, __shfl_xor_sync(0xffu, r, o));
        if (t == 0) s_max = r;
    }
    __syncthreads();
    const float m = s_max;
    float sum = 0.f;
#pragma unroll
    for (int i = 0; i < 4; i++) { v[i] = expf(v[i] - m); sum += v[i]; }
#pragma unroll
    for (int o = 16; o > 0; o >>= 1) sum += __shfl_xor_sync(~0u, sum, o);
    if ((t & 31) == 0) red[t >> 5] = sum;
    __syncthreads();
    if (t < 8) {
        float r = red[t];
#pragma unroll
        for (int o = 4; o > 0; o >>= 1) r += __shfl_xor_sync(0xffu, r, o);
        if (t == 0) s_inv = 1.0f / r;
    }
    __syncthreads();
    const float inv = s_inv;
#pragma unroll
    for (int i = 0; i < 4; i++)
        split_store(v[i] * inv, ph, pl, row * (size_t)CS + (t + 256 * i));
}

// ---------------------------------------------------------------------------
// mma.sync split-bf16 GEMM: C[128 x BN] = A[128,K] . B[BN,K]^T, K = NC*64.
// acc(fp32 regs) = Ah.Bh + Al.Bh + Ah.Bl.  Double-buffered cp.async pipeline.
// 8 warps: 4 (m) x 2 (n); warp tile 32 x BN/2. SW128-swizzled SMEM, ldmatrix.
// MODE 0: C idx = cOff + m*ldc + n (fp32 out or split out, opt bias/gelu/res)
// MODE 1: V-transpose split store to [B,H,DK,S]
// ---------------------------------------------------------------------------
template<int BN, int MODE>
__global__ __launch_bounds__(256)
void mm_gemm(const bf16* __restrict__ Ah, const bf16* __restrict__ Al, long sAo, long sAi, int lda,
             const bf16* __restrict__ Bh, const bf16* __restrict__ Bl, long sBo, long sBi, int ldb,
             float* __restrict__ outf, bf16* __restrict__ outh, bf16* __restrict__ outl,
             long sCo, long sCi, int ldc,
             const float* __restrict__ bias, const float* __restrict__ res,
             float alpha, int gelu, int NC, int HH)
{
    constexpr int NF  = BN / 16;              // n8-frags per warp
    constexpr int ASZ = 128 * 128;            // 16 KB, one A split operand
    constexpr int BSZ = BN * 128;             // one B split operand
    constexpr int STG = 2 * ASZ + 2 * BSZ;    // stage bytes

    extern __shared__ char smem[];
    const uint32_t sb = (uint32_t)__cvta_generic_to_shared(smem);
    const int tid = threadIdx.x, wid = tid >> 5, lane = tid & 31;
    const int z = blockIdx.z, zo = z / HH, zi = z % HH;
    const int bm = blockIdx.y * 128, bn = blockIdx.x * BN;
    Ah += (size_t)zo * sAo + (size_t)zi * sAi;
    Al += (size_t)zo * sAo + (size_t)zi * sAi;
    Bh += (size_t)zo * sBo + (size_t)zi * sBi;
    Bl += (size_t)zo * sBo + (size_t)zi * sBi;
    const size_t cOff = (size_t)zo * sCo + (size_t)zi * sCi;

    const int wm = (wid & 3) * 32;            // warp m offset
    const int wn = (wid >> 2) * (BN / 2);     // warp n offset

    auto load_chunk = [&](int c, int s) {
        const uint32_t base = sb + s * STG;
        const int k0 = c * 64;
#pragma unroll
        for (int i = 0; i < 4; i++) {                 // A: 1024 16B units / split
            int u = tid + i * 256, r = u >> 3, cu = u & 7;
            uint32_t d = base + SWZ(r * 128 + cu * 16);
            size_t g = (size_t)(bm + r) * lda + k0 + cu * 8;
            CP16(d,       Ah + g);
            CP16(d + ASZ, Al + g);
        }
#pragma unroll
        for (int i = 0; i < BN / 32; i++) {           // B: BN*8 units / split
            int u = tid + i * 256, r = u >> 3, cu = u & 7;
            uint32_t d = base + 2 * ASZ + SWZ(r * 128 + cu * 16);
            size_t g = (size_t)(bn + r) * ldb + k0 + cu * 8;
            CP16(d,       Bh + g);
            CP16(d + BSZ, Bl + g);
        }
    };

    float acc[2][NF][4];
#pragma unroll
    for (int mi = 0; mi < 2; mi++)
#pragma unroll
        for (int ni = 0; ni < NF; ni++)
#pragma unroll
            for (int cc = 0; cc < 4; cc++) acc[mi][ni][cc] = 0.f;

    load_chunk(0, 0);
    asm volatile("cp.async.commit_group;" ::: "memory");

    const int li = lane >> 3, lj = lane & 7;          // ldmatrix lane decode

    for (int c = 0; c < NC; c++) {
        const int s = c & 1;
        if (c + 1 < NC) {
            load_chunk(c + 1, (c + 1) & 1);
            asm volatile("cp.async.commit_group;" ::: "memory");
            asm volatile("cp.async.wait_group 1;" ::: "memory");
        } else {
            asm volatile("cp.async.wait_group 0;" ::: "memory");
        }
        __syncthreads();

        const uint32_t aBase = sb + s * STG;
        const uint32_t bBase = aBase + 2 * ASZ;

#pragma unroll
        for (int ks = 0; ks < 4; ks++) {
            const int kb = ks * 16;
            // A frags: matrices (m0-7,k0),(m8-15,k0),(m0-7,k8),(m8-15,k8)
            uint32_t ah[2][4], al[2][4];
#pragma unroll
            for (int mi = 0; mi < 2; mi++) {
                int row = wm + mi * 16 + ((li & 1) << 3) + lj;
                int col = kb + ((li >> 1) << 3);
                uint32_t off = SWZ(row * 128 + col * 2);
                LDSM4(ah[mi], aBase + off);
                LDSM4(al[mi], aBase + ASZ + off);
            }
            // Bh frags: per n16 tile, matrices (n0-7,k0),(n0-7,k8),(n8-15,k0),(n8-15,k8)
            uint32_t bh[NF][2];
#pragma unroll
            for (int nt = 0; nt < NF / 2; nt++) {
                int row = wn + nt * 16 + ((li >> 1) << 3) + lj;
                int col = kb + ((li & 1) << 3);
                uint32_t r4[4];
                LDSM4(r4, bBase + SWZ(row * 128 + col * 2));
                bh[2 * nt][0] = r4[0]; bh[2 * nt][1] = r4[1];
                bh[2 * nt + 1][0] = r4[2]; bh[2 * nt + 1][1] = r4[3];
            }
#pragma unroll
            for (int mi = 0; mi < 2; mi++)
#pragma unroll
                for (int ni = 0; ni < NF; ni++) MMA(acc[mi][ni], ah[mi], bh[ni]);
#pragma unroll
            for (int mi = 0; mi < 2; mi++)
#pragma unroll
                for (int ni = 0; ni < NF; ni++) MMA(acc[mi][ni], al[mi], bh[ni]);
            // Bl frags (reuse pattern), pass Ah.Bl
            uint32_t bl[NF][2];
#pragma unroll
            for (int nt = 0; nt < NF / 2; nt++) {
                int row = wn + nt * 16 + ((li >> 1) << 3) + lj;
                int col = kb + ((li & 1) << 3);
                uint32_t r4[4];
                LDSM4(r4, bBase + BSZ + SWZ(row * 128 + col * 2));
                bl[2 * nt][0] = r4[0]; bl[2 * nt][1] = r4[1];
                bl[2 * nt + 1][0] = r4[2]; bl[2 * nt + 1][1] = r4[3];
            }
#pragma unroll
            for (int mi = 0; mi < 2; mi++)
#pragma unroll
                for (int ni = 0; ni < NF; ni++) MMA(acc[mi][ni], ah[mi], bl[ni]);
        }
        __syncthreads();
    }

    // Epilogue: alpha -> +bias -> gelu -> (+res) -> store
#pragma unroll
    for (int mi = 0; mi < 2; mi++) {
#pragma unroll
        for (int ni = 0; ni < NF; ni++) {
            const int m0 = bm + wm + mi * 16 + (lane >> 2);
            const int n0 = bn + wn + ni * 8 + ((lane & 3) << 1);
#pragma unroll
            for (int rr = 0; rr < 2; rr++) {
                const int m = m0 + rr * 8;
                float v0 = acc[mi][ni][2 * rr + 0] * alpha;
                float v1 = acc[mi][ni][2 * rr + 1] * alpha;
                if (bias) { v0 += bias[n0]; v1 += bias[n0 + 1]; }
                if (gelu) { v0 = gelu_f(v0); v1 = gelu_f(v1); }
                if (MODE == 0) {
                    size_t idx = cOff + (size_t)m * ldc + n0;
                    if (res) { v0 += res[idx]; v1 += res[idx + 1]; }
                    if (outf) {
                        outf[idx] = v0; outf[idx + 1] = v1;
                    } else {
                        bf16 h0 = __float2bfloat16(v0), h1 = __float2bfloat16(v1);
                        __nv_bfloat162 hp; hp.x = h0; hp.y = h1;
                        __nv_bfloat162 lp;
                        lp.x = __float2bfloat16(v0 - __bfloat162float(h0));
                        lp.y = __float2bfloat16(v1 - __bfloat162float(h1));
                        *reinterpret_cast<__nv_bfloat162*>(&outh[idx]) = hp;
                        *reinterpret_cast<__nv_bfloat162*>(&outl[idx]) = lp;
                    }
                } else {
                    // V^T: [B,H,DK,S]; m = b*1024+s, n = h*64+dk
                    size_t i0 = ((size_t)((m >> 10) * CH + (n0 >> 6)) * 64 + (n0 & 63)) * CS + (m & 1023);
                    size_t i1 = ((size_t)((m >> 10) * CH + ((n0 + 1) >> 6)) * 64 + ((n0 + 1) & 63)) * CS + (m & 1023);
                    split_store(v0, outh, outl, i0);
                    split_store(v1, outh, outl, i1);
                }
            }
        }
    }
}

// ---------------------------------------------------------------------------
extern "C" void kernel_launch(void* const* d_in, const int* in_sizes, int n_in,
                              void* d_out, int out_size)
{
    const float* x    = (const float*)d_in[0];
    const int*   mask = (const int*)  d_in[1];
    const float* wq = (const float*)d_in[2],  *bq = (const float*)d_in[3];
    const float* wk = (const float*)d_in[4],  *bk = (const float*)d_in[5];
    const float* wv = (const float*)d_in[6],  *bv = (const float*)d_in[7];
    const float* wo = (const float*)d_in[8],  *bo = (const float*)d_in[9];
    const float* w1 = (const float*)d_in[10], *b1 = (const float*)d_in[11];
    const float* w2 = (const float*)d_in[12], *b2 = (const float*)d_in[13];
    const float* g1 = (const float*)d_in[14], *be1 = (const float*)d_in[15];
    const float* g2 = (const float*)d_in[16], *be2 = (const float*)d_in[17];
    float* out = (float*)d_out;

    bf16 *xnh,*xnl,*qh,*ql,*kh,*kl,*vth,*vtl,*oh,*ol,*h1h,*h1l,*ph,*pl;
    bf16 *wqh,*wql,*wkh,*wkl,*wvh,*wvl,*woh,*wol,*w1h,*w1l,*w2h,*w2l;
    float *sc;
    cudaGetSymbolAddress((void**)&xnh, g_xnh); cudaGetSymbolAddress((void**)&xnl, g_xnl);
    cudaGetSymbolAddress((void**)&qh, g_qh);   cudaGetSymbolAddress((void**)&ql, g_ql);
    cudaGetSymbolAddress((void**)&kh, g_kh);   cudaGetSymbolAddress((void**)&kl, g_kl);
    cudaGetSymbolAddress((void**)&vth, g_vth); cudaGetSymbolAddress((void**)&vtl, g_vtl);
    cudaGetSymbolAddress((void**)&oh, g_oh);   cudaGetSymbolAddress((void**)&ol, g_ol);
    cudaGetSymbolAddress((void**)&h1h, g_h1h); cudaGetSymbolAddress((void**)&h1l, g_h1l);
    cudaGetSymbolAddress((void**)&ph, g_ph);   cudaGetSymbolAddress((void**)&pl, g_pl);
    cudaGetSymbolAddress((void**)&sc, g_sc);
    cudaGetSymbolAddress((void**)&wqh, g_wqh); cudaGetSymbolAddress((void**)&wql, g_wql);
    cudaGetSymbolAddress((void**)&wkh, g_wkh); cudaGetSymbolAddress((void**)&wkl, g_wkl);
    cudaGetSymbolAddress((void**)&wvh, g_wvh); cudaGetSymbolAddress((void**)&wvl, g_wvl);
    cudaGetSymbolAddress((void**)&woh, g_woh); cudaGetSymbolAddress((void**)&wol, g_wol);
    cudaGetSymbolAddress((void**)&w1h, g_w1h); cudaGetSymbolAddress((void**)&w1l, g_w1l);
    cudaGetSymbolAddress((void**)&w2h, g_w2h); cudaGetSymbolAddress((void**)&w2l, g_w2l);

    const int SM128 = 2 * (2 * 16384 + 2 * 128 * 128);   // 131072
    const int SM64  = 2 * (2 * 16384 + 2 * 64 * 128);    // 98304
    cudaFuncSetAttribute(mm_gemm<128,0>, cudaFuncAttributeMaxDynamicSharedMemorySize, SM128);
    cudaFuncSetAttribute(mm_gemm<128,1>, cudaFuncAttributeMaxDynamicSharedMemorySize, SM128);
    cudaFuncSetAttribute(mm_gemm<64,0>,  cudaFuncAttributeMaxDynamicSharedMemorySize, SM64);

    // weight splits
    split_kernel<<<4096, 256>>>(wq, wqh, wql, CD * CD);
    split_kernel<<<4096, 256>>>(wk, wkh, wkl, CD * CD);
    split_kernel<<<4096, 256>>>(wv, wvh, wvl, CD * CD);
    split_kernel<<<4096, 256>>>(wo, woh, wol, CD * CD);
    split_kernel<<<16384, 256>>>(w1, w1h, w1l, CDFF * CD);
    split_kernel<<<16384, 256>>>(w2, w2h, w2l, CD * CDFF);

    // LN1 -> xn (split)
    ln_split_kernel<<<NTOK, 256>>>(x, g1, be1, xnh, xnl);

    // QKV projections (V written transposed [B,H,DK,S])
    dim3 gD(CD / 128, NTOK / 128, 1);
    mm_gemm<128,0><<<gD, 256, SM128>>>(xnh, xnl, 0, 0, CD,  wqh, wql, 0, 0, CD,
        nullptr, qh, ql, 0, 0, CD, bq, nullptr, 1.f, 0, 16, 1);
    mm_gemm<128,0><<<gD, 256, SM128>>>(xnh, xnl, 0, 0, CD,  wkh, wkl, 0, 0, CD,
        nullptr, kh, kl, 0, 0, CD, bk, nullptr, 1.f, 0, 16, 1);
    mm_gemm<128,1><<<gD, 256, SM128>>>(xnh, xnl, 0, 0, CD,  wvh, wvl, 0, 0, CD,
        nullptr, vth, vtl, 0, 0, CD, bv, nullptr, 1.f, 0, 16, 1);

    // scores = 0.125 * Q K^T  (fp32)
    dim3 gS(CS / 128, CS / 128, CB * CH);
    mm_gemm<128,0><<<gS, 256, SM128>>>(
        qh, ql, (long)CS * CD, CDK, CD,
        kh, kl, (long)CS * CD, CDK, CD,
        sc, nullptr, nullptr, (long)CH * CS * CS, (long)CS * CS, CS,
        nullptr, nullptr, 0.125f, 0, 1, CH);

    // masked softmax -> split probs
    softmax_split_kernel<<<CB * CH * CS, 256>>>(sc, mask, ph, pl);

    // O = P V (via V^T, K-major), split into [B,S,D]
    dim3 gP(1, CS / 128, CB * CH);
    mm_gemm<64,0><<<gP, 256, SM64>>>(
        ph, pl, (long)CH * CS * CS, (long)CS * CS, CS,
        vth, vtl, (long)CS * CD, (long)CDK * CS, CS,
        nullptr, oh, ol, (long)CS * CD, CDK, CD,
        nullptr, nullptr, 1.f, 0, 16, CH);

    // x1 = O wo^T + bo + x -> out (fp32)
    mm_gemm<128,0><<<gD, 256, SM128>>>(oh, ol, 0, 0, CD,  woh, wol, 0, 0, CD,
        out, nullptr, nullptr, 0, 0, CD, bo, x, 1.f, 0, 16, 1);

    // LN2 -> xn (split)
    ln_split_kernel<<<NTOK, 256>>>(out, g2, be2, xnh, xnl);

    // h1 = gelu(xn w1^T + b1) (split)
    dim3 gF(CDFF / 128, NTOK / 128, 1);
    mm_gemm<128,0><<<gF, 256, SM128>>>(xnh, xnl, 0, 0, CD,  w1h, w1l, 0, 0, CD,
        nullptr, h1h, h1l, 0, 0, CDFF, b1, nullptr, 1.f, 1, 16, 1);

    // out = x1 + h1 w2^T + b2
    mm_gemm<128,0><<<gD, 256, SM128>>>(h1h, h1l, 0, 0, CDFF,  w2h, w2l, 0, 0, CDFF,
        out, nullptr, nullptr, 0, 0, CD, b2, out, 1.f, 0, 64, 1);
}

// round 5
// speedup vs baseline: 3.3391x; 1.1795x over previous
#include <cuda_runtime.h>
#include <cuda_bf16.h>
#include <math.h>
#include <stdint.h>

#define CB 8
#define CS 1024
#define CD 1024
#define CH 16
#define CDK 64
#define CDFF 4096
#define NTOK (CB*CS)
typedef __nv_bfloat16 bf16;

#define SWZ(o) ((o) ^ (((o) >> 3) & 0x70))
#define CP16(dst, src) asm volatile("cp.async.cg.shared.global [%0], [%1], 16;" :: "r"(dst), "l"(src) : "memory")

#define LDSM4(r, a) \
    asm volatile("ldmatrix.sync.aligned.m8n8.x4.shared.b16 {%0,%1,%2,%3}, [%4];" \
        : "=r"((r)[0]), "=r"((r)[1]), "=r"((r)[2]), "=r"((r)[3]) : "r"(a))
#define LDSM4T(r, a) \
    asm volatile("ldmatrix.sync.aligned.m8n8.x4.trans.shared.b16 {%0,%1,%2,%3}, [%4];" \
        : "=r"((r)[0]), "=r"((r)[1]), "=r"((r)[2]), "=r"((r)[3]) : "r"(a))

#define MMA(c, a, b) \
    asm volatile("mma.sync.aligned.m16n8k16.row.col.f32.bf16.bf16.f32 " \
        "{%0,%1,%2,%3},{%4,%5,%6,%7},{%8,%9},{%0,%1,%2,%3};" \
        : "+f"((c)[0]), "+f"((c)[1]), "+f"((c)[2]), "+f"((c)[3]) \
        : "r"((a)[0]), "r"((a)[1]), "r"((a)[2]), "r"((a)[3]), "r"((b)[0]), "r"((b)[1]))

__device__ __forceinline__ float gelu_f(float x) {
    float x3 = x * x * x;
    return 0.5f * x * (1.0f + tanhf(0.7978845608028654f * (x + 0.044715f * x3)));
}
__device__ __forceinline__ void split_store(float v, bf16* h, bf16* l, size_t i) {
    bf16 hi = __float2bfloat16(v);
    h[i] = hi;
    l[i] = __float2bfloat16(v - __bfloat162float(hi));
}
__device__ __forceinline__ uint32_t packbf2(float a, float b) {
    __nv_bfloat162 t = __floats2bfloat162_rn(a, b);
    return *reinterpret_cast<uint32_t*>(&t);
}

// ------------------------- scratch -------------------------
__device__ bf16 g_xnh[NTOK*CD], g_xnl[NTOK*CD];
__device__ bf16 g_qh[NTOK*CD],  g_ql[NTOK*CD];
__device__ bf16 g_kh[NTOK*CD],  g_kl[NTOK*CD];
__device__ bf16 g_vh[NTOK*CD],  g_vl[NTOK*CD];
__device__ bf16 g_oh[NTOK*CD],  g_ol[NTOK*CD];
__device__ bf16 g_h1h[(size_t)NTOK*CDFF], g_h1l[(size_t)NTOK*CDFF];
__device__ bf16 g_wqh[CD*CD], g_wql[CD*CD], g_wkh[CD*CD], g_wkl[CD*CD];
__device__ bf16 g_wvh[CD*CD], g_wvl[CD*CD], g_woh[CD*CD], g_wol[CD*CD];
__device__ bf16 g_w1h[(size_t)CDFF*CD], g_w1l[(size_t)CDFF*CD];
__device__ bf16 g_w2h[(size_t)CD*CDFF], g_w2l[(size_t)CD*CDFF];

__global__ __launch_bounds__(256)
void split_kernel(const float* __restrict__ w, bf16* __restrict__ h, bf16* __restrict__ l, int n) {
    int i = blockIdx.x * 256 + threadIdx.x;
    if (i < n) split_store(w[i], h, l, (size_t)i);
}

// ------------------------- LayerNorm (ddof=1, eps on std) -> split -------------------------
__global__ __launch_bounds__(256)
void ln_split_kernel(const float* __restrict__ x, const float* __restrict__ gamma,
                     const float* __restrict__ beta, bf16* __restrict__ oh, bf16* __restrict__ ol) {
    const int row = blockIdx.x;
    const float* xr = x + (size_t)row * CD;
    const int t = threadIdx.x;
    float v[4];
#pragma unroll
    for (int i = 0; i < 4; i++) v[i] = xr[t + 256 * i];
    __shared__ float red[8];
    __shared__ float s_mean, s_rstd;
    float s = v[0] + v[1] + v[2] + v[3];
#pragma unroll
    for (int o = 16; o > 0; o >>= 1) s += __shfl_xor_sync(~0u, s, o);
    if ((t & 31) == 0) red[t >> 5] = s;
    __syncthreads();
    if (t < 8) {
        float r = red[t];
#pragma unroll
        for (int o = 4; o > 0; o >>= 1) r += __shfl_xor_sync(0xffu, r, o);
        if (t == 0) s_mean = r * (1.0f / CD);
    }
    __syncthreads();
    const float mean = s_mean;
    float q = 0.f;
#pragma unroll
    for (int i = 0; i < 4; i++) { float d = v[i] - mean; q += d * d; }
#pragma unroll
    for (int o = 16; o > 0; o >>= 1) q += __shfl_xor_sync(~0u, q, o);
    if ((t & 31) == 0) red[t >> 5] = q;
    __syncthreads();
    if (t < 8) {
        float r = red[t];
#pragma unroll
        for (int o = 4; o > 0; o >>= 1) r += __shfl_xor_sync(0xffu, r, o);
        if (t == 0) s_rstd = 1.0f / (sqrtf(r * (1.0f / (CD - 1))) + 1e-5f);
    }
    __syncthreads();
    const float rstd = s_rstd;
#pragma unroll
    for (int i = 0; i < 4; i++) {
        int c = t + 256 * i;
        split_store(gamma[c] * (v[i] - mean) * rstd + beta[c], oh, ol, (size_t)row * CD + c);
    }
}

// ---------------------------------------------------------------------------
// Flash attention: O = softmax(mask(0.125 * Q K^T)) V, one (b,h,qtile) per CTA.
// Q/K/V split bf16 in [B,S,H*DK]; online softmax; 3-pass split MMA both GEMMs.
// 8 warps x 16 q-rows. K/V tiles (128 x 64) double-buffered via cp.async.
// ---------------------------------------------------------------------------
__global__ __launch_bounds__(256, 1)
void flash_kernel(const bf16* __restrict__ Qh, const bf16* __restrict__ Ql,
                  const bf16* __restrict__ Kh, const bf16* __restrict__ Kl,
                  const bf16* __restrict__ Vh, const bf16* __restrict__ Vl,
                  const int* __restrict__ mask,
                  bf16* __restrict__ Oh, bf16* __restrict__ Ol)
{
    extern __shared__ char smem[];
    const uint32_t sb = (uint32_t)__cvta_generic_to_shared(smem);
    const int tid = threadIdx.x, wid = tid >> 5, lane = tid & 31;
    const int qt = blockIdx.x, z = blockIdx.y;
    const int b = z >> 4, h = z & 15;
    const int qbase = qt * 128;
    const size_t headOff = (size_t)h * 64;

    auto gaddr = [&](const bf16* base, int srow, int cu) {
        return base + ((size_t)(b * CS + srow) * CD + headOff + (cu << 3));
    };

    // Q tiles (hi @0, lo @16384)
#pragma unroll
    for (int i = 0; i < 4; i++) {
        int u = tid + i * 256, r = u >> 3, cu = u & 7;
        uint32_t d = sb + SWZ(r * 128 + cu * 16);
        CP16(d,         gaddr(Qh, qbase + r, cu));
        CP16(d + 16384, gaddr(Ql, qbase + r, cu));
    }

    auto loadKV = [&](int it, int s) {
        const uint32_t base = sb + 32768 + s * 65536;
        const int kb = it * 128;
#pragma unroll
        for (int i = 0; i < 4; i++) {
            int u = tid + i * 256, r = u >> 3, cu = u & 7;
            uint32_t sw = SWZ(r * 128 + cu * 16);
            CP16(base + sw,         gaddr(Kh, kb + r, cu));
            CP16(base + 16384 + sw, gaddr(Kl, kb + r, cu));
            CP16(base + 32768 + sw, gaddr(Vh, kb + r, cu));
            CP16(base + 49152 + sw, gaddr(Vl, kb + r, cu));
        }
    };

    loadKV(0, 0);
    asm volatile("cp.async.commit_group;" ::: "memory");
    loadKV(1, 1);
    asm volatile("cp.async.commit_group;" ::: "memory");

    float oacc[8][4];
#pragma unroll
    for (int i = 0; i < 8; i++)
#pragma unroll
        for (int j = 0; j < 4; j++) oacc[i][j] = 0.f;
    float m_old[2] = {-INFINITY, -INFINITY};
    float l_sum[2] = {0.f, 0.f};

    const int li = lane >> 3, lj = lane & 7;
    const int rbase = wid * 16 + (lane >> 2);

    for (int it = 0; it < 8; it++) {
        const int s = it & 1;
        if (it < 7) asm volatile("cp.async.wait_group 1;" ::: "memory");
        else        asm volatile("cp.async.wait_group 0;" ::: "memory");
        __syncthreads();

        const uint32_t kst = sb + 32768 + s * 65536;
        const uint32_t vst = kst + 32768;

        // ---- S = Q K^T (3-pass split) ----
        float sacc[16][4];
#pragma unroll
        for (int i = 0; i < 16; i++)
#pragma unroll
            for (int j = 0; j < 4; j++) sacc[i][j] = 0.f;

#pragma unroll
        for (int kk = 0; kk < 4; kk++) {
            uint32_t ah[4], al[4];
            uint32_t aoff = SWZ((wid * 16 + ((li & 1) << 3) + lj) * 128 + (kk * 16 + ((li >> 1) << 3)) * 2);
            LDSM4(ah, sb + aoff);
            LDSM4(al, sb + 16384 + aoff);
            uint32_t bh[8][4];
#pragma unroll
            for (int nt = 0; nt < 8; nt++) {
                uint32_t off = SWZ((nt * 16 + ((li >> 1) << 3) + lj) * 128 + (kk * 16 + ((li & 1) << 3)) * 2);
                LDSM4(bh[nt], kst + off);
            }
#pragma unroll
            for (int nt = 0; nt < 8; nt++) { MMA(sacc[2*nt], ah, bh[nt]); MMA(sacc[2*nt+1], ah, bh[nt]+2); }
#pragma unroll
            for (int nt = 0; nt < 8; nt++) { MMA(sacc[2*nt], al, bh[nt]); MMA(sacc[2*nt+1], al, bh[nt]+2); }
#pragma unroll
            for (int nt = 0; nt < 8; nt++) {
                uint32_t off = SWZ((nt * 16 + ((li >> 1) << 3) + lj) * 128 + (kk * 16 + ((li & 1) << 3)) * 2);
                LDSM4(bh[nt], kst + 16384 + off);
            }
#pragma unroll
            for (int nt = 0; nt < 8; nt++) { MMA(sacc[2*nt], ah, bh[nt]); MMA(sacc[2*nt+1], ah, bh[nt]+2); }
        }

        // ---- mask, scale, online softmax ----
#pragma unroll
        for (int rr = 0; rr < 2; rr++) {
            const int grow = qbase + rbase + rr * 8;
            const int2* mrow = (const int2*)(mask + ((size_t)(b * CS + grow)) * CS + it * 128 + ((lane & 3) << 1));
            float mx = -INFINITY;
#pragma unroll
            for (int ni = 0; ni < 16; ni++) {
                int2 mv = mrow[ni * 4];
                float v0 = mv.x ? sacc[ni][2*rr]   * 0.125f : -1e9f;
                float v1 = mv.y ? sacc[ni][2*rr+1] * 0.125f : -1e9f;
                sacc[ni][2*rr] = v0; sacc[ni][2*rr+1] = v1;
                mx = fmaxf(mx, fmaxf(v0, v1));
            }
            mx = fmaxf(mx, __shfl_xor_sync(~0u, mx, 1));
            mx = fmaxf(mx, __shfl_xor_sync(~0u, mx, 2));
            const float mnew = fmaxf(m_old[rr], mx);
            const float scl = expf(m_old[rr] - mnew);
            float rsum = 0.f;
#pragma unroll
            for (int ni = 0; ni < 16; ni++) {
                float p0 = expf(sacc[ni][2*rr]   - mnew);
                float p1 = expf(sacc[ni][2*rr+1] - mnew);
                sacc[ni][2*rr] = p0; sacc[ni][2*rr+1] = p1;
                rsum += p0 + p1;
            }
            rsum += __shfl_xor_sync(~0u, rsum, 1);
            rsum += __shfl_xor_sync(~0u, rsum, 2);
            l_sum[rr] = l_sum[rr] * scl + rsum;
            m_old[rr] = mnew;
#pragma unroll
            for (int ni = 0; ni < 8; ni++) { oacc[ni][2*rr] *= scl; oacc[ni][2*rr+1] *= scl; }
        }

        // ---- O += P V (3-pass split; P from registers, V via ldmatrix.trans) ----
#pragma unroll
        for (int kk = 0; kk < 8; kk++) {
            uint32_t ah2[4], al2[4];
            const int f0 = 2 * kk, f1 = 2 * kk + 1;
            {
                __nv_bfloat162 h0 = __floats2bfloat162_rn(sacc[f0][0], sacc[f0][1]);
                __nv_bfloat162 h1 = __floats2bfloat162_rn(sacc[f0][2], sacc[f0][3]);
                __nv_bfloat162 h2 = __floats2bfloat162_rn(sacc[f1][0], sacc[f1][1]);
                __nv_bfloat162 h3 = __floats2bfloat162_rn(sacc[f1][2], sacc[f1][3]);
                ah2[0] = *reinterpret_cast<uint32_t*>(&h0);
                ah2[1] = *reinterpret_cast<uint32_t*>(&h1);
                ah2[2] = *reinterpret_cast<uint32_t*>(&h2);
                ah2[3] = *reinterpret_cast<uint32_t*>(&h3);
                al2[0] = packbf2(sacc[f0][0] - __low2float(h0),  sacc[f0][1] - __high2float(h0));
                al2[1] = packbf2(sacc[f0][2] - __low2float(h1),  sacc[f0][3] - __high2float(h1));
                al2[2] = packbf2(sacc[f1][0] - __low2float(h2),  sacc[f1][1] - __high2float(h2));
                al2[3] = packbf2(sacc[f1][2] - __low2float(h3),  sacc[f1][3] - __high2float(h3));
            }
            uint32_t vf[4][4];
#pragma unroll
            for (int nb = 0; nb < 4; nb++) {
                uint32_t off = SWZ((kk * 16 + ((li & 1) << 3) + lj) * 128 + (nb * 16 + ((li >> 1) << 3)) * 2);
                LDSM4T(vf[nb], vst + off);
            }
#pragma unroll
            for (int nb = 0; nb < 4; nb++) { MMA(oacc[2*nb], ah2, vf[nb]); MMA(oacc[2*nb+1], ah2, vf[nb]+2); }
#pragma unroll
            for (int nb = 0; nb < 4; nb++) { MMA(oacc[2*nb], al2, vf[nb]); MMA(oacc[2*nb+1], al2, vf[nb]+2); }
#pragma unroll
            for (int nb = 0; nb < 4; nb++) {
                uint32_t off = SWZ((kk * 16 + ((li & 1) << 3) + lj) * 128 + (nb * 16 + ((li >> 1) << 3)) * 2);
                LDSM4T(vf[nb], vst + 16384 + off);
            }
#pragma unroll
            for (int nb = 0; nb < 4; nb++) { MMA(oacc[2*nb], ah2, vf[nb]); MMA(oacc[2*nb+1], ah2, vf[nb]+2); }
        }

        __syncthreads();
        if (it + 2 < 8) {
            loadKV(it + 2, s);
            asm volatile("cp.async.commit_group;" ::: "memory");
        }
    }

    // ---- normalize + split store O [B,S,H*DK] ----
#pragma unroll
    for (int rr = 0; rr < 2; rr++) {
        const int grow = qbase + rbase + rr * 8;
        const float inv = 1.f / l_sum[rr];
        const size_t base = (size_t)(b * CS + grow) * CD + headOff + ((lane & 3) << 1);
#pragma unroll
        for (int ni = 0; ni < 8; ni++) {
            float v0 = oacc[ni][2*rr] * inv, v1 = oacc[ni][2*rr+1] * inv;
            __nv_bfloat162 hp = __floats2bfloat162_rn(v0, v1);
            __nv_bfloat162 lp = __floats2bfloat162_rn(v0 - __low2float(hp), v1 - __high2float(hp));
            *reinterpret_cast<__nv_bfloat162*>(&Oh[base + 8 * ni]) = hp;
            *reinterpret_cast<__nv_bfloat162*>(&Ol[base + 8 * ni]) = lp;
        }
    }
}

// ---------------------------------------------------------------------------
// mma.sync split-bf16 GEMM: C[128 x BN] = A[128,K] . B[BN,K]^T, K = NC*64.
// ---------------------------------------------------------------------------
template<int BN>
__global__ __launch_bounds__(256)
void mm_gemm(const bf16* __restrict__ Ah, const bf16* __restrict__ Al, int lda,
             const bf16* __restrict__ Bh, const bf16* __restrict__ Bl, int ldb,
             float* __restrict__ outf, bf16* __restrict__ outh, bf16* __restrict__ outl, int ldc,
             const float* __restrict__ bias, const float* __restrict__ res,
             int gelu, int NC)
{
    constexpr int NF  = BN / 16;
    constexpr int ASZ = 128 * 128;
    constexpr int BSZ = BN * 128;
    constexpr int STG = 2 * ASZ + 2 * BSZ;

    extern __shared__ char smem[];
    const uint32_t sb = (uint32_t)__cvta_generic_to_shared(smem);
    const int tid = threadIdx.x, wid = tid >> 5, lane = tid & 31;
    const int bm = blockIdx.y * 128, bn = blockIdx.x * BN;

    const int wm = (wid & 3) * 32;
    const int wn = (wid >> 2) * (BN / 2);

    auto load_chunk = [&](int c, int s) {
        const uint32_t base = sb + s * STG;
        const int k0 = c * 64;
#pragma unroll
        for (int i = 0; i < 4; i++) {
            int u = tid + i * 256, r = u >> 3, cu = u & 7;
            uint32_t d = base + SWZ(r * 128 + cu * 16);
            size_t g = (size_t)(bm + r) * lda + k0 + cu * 8;
            CP16(d,       Ah + g);
            CP16(d + ASZ, Al + g);
        }
#pragma unroll
        for (int i = 0; i < BN / 32; i++) {
            int u = tid + i * 256, r = u >> 3, cu = u & 7;
            uint32_t d = base + 2 * ASZ + SWZ(r * 128 + cu * 16);
            size_t g = (size_t)(bn + r) * ldb + k0 + cu * 8;
            CP16(d,       Bh + g);
            CP16(d + BSZ, Bl + g);
        }
    };

    float acc[2][NF][4];
#pragma unroll
    for (int mi = 0; mi < 2; mi++)
#pragma unroll
        for (int ni = 0; ni < NF; ni++)
#pragma unroll
            for (int cc = 0; cc < 4; cc++) acc[mi][ni][cc] = 0.f;

    load_chunk(0, 0);
    asm volatile("cp.async.commit_group;" ::: "memory");

    const int li = lane >> 3, lj = lane & 7;

    for (int c = 0; c < NC; c++) {
        const int s = c & 1;
        if (c + 1 < NC) {
            load_chunk(c + 1, (c + 1) & 1);
            asm volatile("cp.async.commit_group;" ::: "memory");
            asm volatile("cp.async.wait_group 1;" ::: "memory");
        } else {
            asm volatile("cp.async.wait_group 0;" ::: "memory");
        }
        __syncthreads();

        const uint32_t aBase = sb + s * STG;
        const uint32_t bBase = aBase + 2 * ASZ;

#pragma unroll
        for (int ks = 0; ks < 4; ks++) {
            const int kb = ks * 16;
            uint32_t ah[2][4], al[2][4];
#pragma unroll
            for (int mi = 0; mi < 2; mi++) {
                int row = wm + mi * 16 + ((li & 1) << 3) + lj;
                int col = kb + ((li >> 1) << 3);
                uint32_t off = SWZ(row * 128 + col * 2);
                LDSM4(ah[mi], aBase + off);
                LDSM4(al[mi], aBase + ASZ + off);
            }
            uint32_t bh[NF][2];
#pragma unroll
            for (int nt = 0; nt < NF / 2; nt++) {
                int row = wn + nt * 16 + ((li >> 1) << 3) + lj;
                int col = kb + ((li & 1) << 3);
                uint32_t r4[4];
                LDSM4(r4, bBase + SWZ(row * 128 + col * 2));
                bh[2*nt][0] = r4[0]; bh[2*nt][1] = r4[1];
                bh[2*nt+1][0] = r4[2]; bh[2*nt+1][1] = r4[3];
            }
#pragma unroll
            for (int mi = 0; mi < 2; mi++)
#pragma unroll
                for (int ni = 0; ni < NF; ni++) MMA(acc[mi][ni], ah[mi], bh[ni]);
#pragma unroll
            for (int mi = 0; mi < 2; mi++)
#pragma unroll
                for (int ni = 0; ni < NF; ni++) MMA(acc[mi][ni], al[mi], bh[ni]);
            uint32_t bl[NF][2];
#pragma unroll
            for (int nt = 0; nt < NF / 2; nt++) {
                int row = wn + nt * 16 + ((li >> 1) << 3) + lj;
                int col = kb + ((li & 1) << 3);
                uint32_t r4[4];
                LDSM4(r4, bBase + BSZ + SWZ(row * 128 + col * 2));
                bl[2*nt][0] = r4[0]; bl[2*nt][1] = r4[1];
                bl[2*nt+1][0] = r4[2]; bl[2*nt+1][1] = r4[3];
            }
#pragma unroll
            for (int mi = 0; mi < 2; mi++)
#pragma unroll
                for (int ni = 0; ni < NF; ni++) MMA(acc[mi][ni], ah[mi], bl[ni]);
        }
        __syncthreads();
    }

#pragma unroll
    for (int mi = 0; mi < 2; mi++) {
#pragma unroll
        for (int ni = 0; ni < NF; ni++) {
            const int m0 = bm + wm + mi * 16 + (lane >> 2);
            const int n0 = bn + wn + ni * 8 + ((lane & 3) << 1);
#pragma unroll
            for (int rr = 0; rr < 2; rr++) {
                const int m = m0 + rr * 8;
                float v0 = acc[mi][ni][2*rr + 0];
                float v1 = acc[mi][ni][2*rr + 1];
                if (bias) { v0 += bias[n0]; v1 += bias[n0 + 1]; }
                if (gelu) { v0 = gelu_f(v0); v1 = gelu_f(v1); }
                size_t idx = (size_t)m * ldc + n0;
                if (res) { v0 += res[idx]; v1 += res[idx + 1]; }
                if (outf) {
                    outf[idx] = v0; outf[idx + 1] = v1;
                } else {
                    __nv_bfloat162 hp = __floats2bfloat162_rn(v0, v1);
                    __nv_bfloat162 lp = __floats2bfloat162_rn(v0 - __low2float(hp), v1 - __high2float(hp));
                    *reinterpret_cast<__nv_bfloat162*>(&outh[idx]) = hp;
                    *reinterpret_cast<__nv_bfloat162*>(&outl[idx]) = lp;
                }
            }
        }
    }
}

// ---------------------------------------------------------------------------
extern "C" void kernel_launch(void* const* d_in, const int* in_sizes, int n_in,
                              void* d_out, int out_size)
{
    const float* x    = (const float*)d_in[0];
    const int*   mask = (const int*)  d_in[1];
    const float* wq = (const float*)d_in[2],  *bq = (const float*)d_in[3];
    const float* wk = (const float*)d_in[4],  *bk = (const float*)d_in[5];
    const float* wv = (const float*)d_in[6],  *bv = (const float*)d_in[7];
    const float* wo = (const float*)d_in[8],  *bo = (const float*)d_in[9];
    const float* w1 = (const float*)d_in[10], *b1 = (const float*)d_in[11];
    const float* w2 = (const float*)d_in[12], *b2 = (const float*)d_in[13];
    const float* g1 = (const float*)d_in[14], *be1 = (const float*)d_in[15];
    const float* g2 = (const float*)d_in[16], *be2 = (const float*)d_in[17];
    float* out = (float*)d_out;

    bf16 *xnh,*xnl,*qh,*ql,*kh,*kl,*vh,*vl,*oh,*ol,*h1h,*h1l;
    bf16 *wqh,*wql,*wkh,*wkl,*wvh,*wvl,*woh,*wol,*w1h,*w1l,*w2h,*w2l;
    cudaGetSymbolAddress((void**)&xnh, g_xnh); cudaGetSymbolAddress((void**)&xnl, g_xnl);
    cudaGetSymbolAddress((void**)&qh, g_qh);   cudaGetSymbolAddress((void**)&ql, g_ql);
    cudaGetSymbolAddress((void**)&kh, g_kh);   cudaGetSymbolAddress((void**)&kl, g_kl);
    cudaGetSymbolAddress((void**)&vh, g_vh);   cudaGetSymbolAddress((void**)&vl, g_vl);
    cudaGetSymbolAddress((void**)&oh, g_oh);   cudaGetSymbolAddress((void**)&ol, g_ol);
    cudaGetSymbolAddress((void**)&h1h, g_h1h); cudaGetSymbolAddress((void**)&h1l, g_h1l);
    cudaGetSymbolAddress((void**)&wqh, g_wqh); cudaGetSymbolAddress((void**)&wql, g_wql);
    cudaGetSymbolAddress((void**)&wkh, g_wkh); cudaGetSymbolAddress((void**)&wkl, g_wkl);
    cudaGetSymbolAddress((void**)&wvh, g_wvh); cudaGetSymbolAddress((void**)&wvl, g_wvl);
    cudaGetSymbolAddress((void**)&woh, g_woh); cudaGetSymbolAddress((void**)&wol, g_wol);
    cudaGetSymbolAddress((void**)&w1h, g_w1h); cudaGetSymbolAddress((void**)&w1l, g_w1l);
    cudaGetSymbolAddress((void**)&w2h, g_w2h); cudaGetSymbolAddress((void**)&w2l, g_w2l);

    const int SM128 = 2 * (2 * 16384 + 2 * 128 * 128);   // 131072
    const int SMFL  = 32768 + 2 * 65536;                 // 163840
    cudaFuncSetAttribute(mm_gemm<128>, cudaFuncAttributeMaxDynamicSharedMemorySize, SM128);
    cudaFuncSetAttribute(flash_kernel, cudaFuncAttributeMaxDynamicSharedMemorySize, SMFL);

    // weight splits
    split_kernel<<<4096, 256>>>(wq, wqh, wql, CD * CD);
    split_kernel<<<4096, 256>>>(wk, wkh, wkl, CD * CD);
    split_kernel<<<4096, 256>>>(wv, wvh, wvl, CD * CD);
    split_kernel<<<4096, 256>>>(wo, woh, wol, CD * CD);
    split_kernel<<<16384, 256>>>(w1, w1h, w1l, CDFF * CD);
    split_kernel<<<16384, 256>>>(w2, w2h, w2l, CD * CDFF);

    // LN1 -> xn (split)
    ln_split_kernel<<<NTOK, 256>>>(x, g1, be1, xnh, xnl);

    // QKV projections, all in [B,S,H*DK]
    dim3 gD(CD / 128, NTOK / 128);
    mm_gemm<128><<<gD, 256, SM128>>>(xnh, xnl, CD, wqh, wql, CD,
        nullptr, qh, ql, CD, bq, nullptr, 0, 16);
    mm_gemm<128><<<gD, 256, SM128>>>(xnh, xnl, CD, wkh, wkl, CD,
        nullptr, kh, kl, CD, bk, nullptr, 0, 16);
    mm_gemm<128><<<gD, 256, SM128>>>(xnh, xnl, CD, wvh, wvl, CD,
        nullptr, vh, vl, CD, bv, nullptr, 0, 16);

    // fused attention -> O (split, [B,S,D])
    dim3 gA(CS / 128, CB * CH);
    flash_kernel<<<gA, 256, SMFL>>>(qh, ql, kh, kl, vh, vl, mask, oh, ol);

    // x1 = O wo^T + bo + x -> out (fp32)
    mm_gemm<128><<<gD, 256, SM128>>>(oh, ol, CD, woh, wol, CD,
        out, nullptr, nullptr, CD, bo, x, 0, 16);

    // LN2 -> xn (split)
    ln_split_kernel<<<NTOK, 256>>>(out, g2, be2, xnh, xnl);

    // h1 = gelu(xn w1^T + b1) (split)
    dim3 gF(CDFF / 128, NTOK / 128);
    mm_gemm<128><<<gF, 256, SM128>>>(xnh, xnl, CD, w1h, w1l, CD,
        nullptr, h1h, h1l, CDFF, b1, nullptr, 1, 16);

    // out = x1 + h1 w2^T + b2
    mm_gemm<128><<<gD, 256, SM128>>>(h1h, h1l, CDFF, w2h, w2l, CDFF,
        out, nullptr, nullptr, CD, b2, out, 0, 64);
}

// round 6
// speedup vs baseline: 4.2640x; 1.2770x over previous
#include <cuda_runtime.h>
#include <cuda_fp16.h>
#include <math.h>
#include <stdint.h>

#define CB 8
#define CS 1024
#define CD 1024
#define CH 16
#define CDK 64
#define CDFF 4096
#define NTOK (CB*CS)
typedef __half hf;

#define SWZ(o) ((o) ^ (((o) >> 3) & 0x70))
#define CP16(dst, src) asm volatile("cp.async.cg.shared.global [%0], [%1], 16;" :: "r"(dst), "l"(src) : "memory")

#define LDSM4(r, a) \
    asm volatile("ldmatrix.sync.aligned.m8n8.x4.shared.b16 {%0,%1,%2,%3}, [%4];" \
        : "=r"((r)[0]), "=r"((r)[1]), "=r"((r)[2]), "=r"((r)[3]) : "r"(a))
#define LDSM4T(r, a) \
    asm volatile("ldmatrix.sync.aligned.m8n8.x4.trans.shared.b16 {%0,%1,%2,%3}, [%4];" \
        : "=r"((r)[0]), "=r"((r)[1]), "=r"((r)[2]), "=r"((r)[3]) : "r"(a))

#define MMA(c, a, b) \
    asm volatile("mma.sync.aligned.m16n8k16.row.col.f32.f16.f16.f32 " \
        "{%0,%1,%2,%3},{%4,%5,%6,%7},{%8,%9},{%0,%1,%2,%3};" \
        : "+f"((c)[0]), "+f"((c)[1]), "+f"((c)[2]), "+f"((c)[3]) \
        : "r"((a)[0]), "r"((a)[1]), "r"((a)[2]), "r"((a)[3]), "r"((b)[0]), "r"((b)[1]))

__device__ __forceinline__ float gelu_f(float x) {
    float x3 = x * x * x;
    return 0.5f * x * (1.0f + tanhf(0.7978845608028654f * (x + 0.044715f * x3)));
}
__device__ __forceinline__ void split_store(float v, hf* h, hf* l, size_t i) {
    hf hi = __float2half_rn(v);
    h[i] = hi;
    l[i] = __float2half_rn(v - __half2float(hi));
}
__device__ __forceinline__ uint32_t packh2(float a, float b) {
    __half2 t = __floats2half2_rn(a, b);
    return *reinterpret_cast<uint32_t*>(&t);
}

// ------------------------- scratch -------------------------
__device__ hf g_xnh[NTOK*CD], g_xnl[NTOK*CD];
__device__ hf g_qh[NTOK*CD],  g_ql[NTOK*CD];
__device__ hf g_kh[NTOK*CD];
__device__ hf g_vh[NTOK*CD];
__device__ hf g_oh[NTOK*CD],  g_ol[NTOK*CD];
__device__ hf g_h1h[(size_t)NTOK*CDFF], g_h1l[(size_t)NTOK*CDFF];
__device__ hf g_wq[CD*CD], g_wk[CD*CD], g_wv[CD*CD], g_wo[CD*CD];
__device__ hf g_w1[(size_t)CDFF*CD], g_w2[(size_t)CD*CDFF];

__global__ __launch_bounds__(256)
void conv_kernel(const float* __restrict__ w, hf* __restrict__ h, int n) {
    int i = blockIdx.x * 256 + threadIdx.x;
    if (i < n) h[i] = __float2half_rn(w[i]);
}

// ------------------------- LayerNorm (ddof=1, eps on std) -> split fp16 -------------------------
__global__ __launch_bounds__(256)
void ln_split_kernel(const float* __restrict__ x, const float* __restrict__ gamma,
                     const float* __restrict__ beta, hf* __restrict__ oh, hf* __restrict__ ol) {
    const int row = blockIdx.x;
    const float* xr = x + (size_t)row * CD;
    const int t = threadIdx.x;
    float v[4];
#pragma unroll
    for (int i = 0; i < 4; i++) v[i] = xr[t + 256 * i];
    __shared__ float red[8];
    __shared__ float s_mean, s_rstd;
    float s = v[0] + v[1] + v[2] + v[3];
#pragma unroll
    for (int o = 16; o > 0; o >>= 1) s += __shfl_xor_sync(~0u, s, o);
    if ((t & 31) == 0) red[t >> 5] = s;
    __syncthreads();
    if (t < 8) {
        float r = red[t];
#pragma unroll
        for (int o = 4; o > 0; o >>= 1) r += __shfl_xor_sync(0xffu, r, o);
        if (t == 0) s_mean = r * (1.0f / CD);
    }
    __syncthreads();
    const float mean = s_mean;
    float q = 0.f;
#pragma unroll
    for (int i = 0; i < 4; i++) { float d = v[i] - mean; q += d * d; }
#pragma unroll
    for (int o = 16; o > 0; o >>= 1) q += __shfl_xor_sync(~0u, q, o);
    if ((t & 31) == 0) red[t >> 5] = q;
    __syncthreads();
    if (t < 8) {
        float r = red[t];
#pragma unroll
        for (int o = 4; o > 0; o >>= 1) r += __shfl_xor_sync(0xffu, r, o);
        if (t == 0) s_rstd = 1.0f / (sqrtf(r * (1.0f / (CD - 1))) + 1e-5f);
    }
    __syncthreads();
    const float rstd = s_rstd;
#pragma unroll
    for (int i = 0; i < 4; i++) {
        int c = t + 256 * i;
        split_store(gamma[c] * (v[i] - mean) * rstd + beta[c], oh, ol, (size_t)row * CD + c);
    }
}

// ---------------------------------------------------------------------------
// Flash attention: O = softmax(mask(0.125 * Q K^T)) V.
// Q split hi/lo; K,V fp16 hi only. 2-pass split MMA on both GEMMs.
// SMEM: Q hi 16K, Q lo 16K, 2 stages x (Kh 16K + Vh 16K) = 96 KB -> 2 CTA/SM.
// ---------------------------------------------------------------------------
__global__ __launch_bounds__(256)
void flash_kernel(const hf* __restrict__ Qh, const hf* __restrict__ Ql,
                  const hf* __restrict__ Kh, const hf* __restrict__ Vh,
                  const int* __restrict__ mask,
                  hf* __restrict__ Oh, hf* __restrict__ Ol)
{
    extern __shared__ char smem[];
    const uint32_t sb = (uint32_t)__cvta_generic_to_shared(smem);
    const int tid = threadIdx.x, wid = tid >> 5, lane = tid & 31;
    const int qt = blockIdx.x, z = blockIdx.y;
    const int b = z >> 4, h = z & 15;
    const int qbase = qt * 128;
    const size_t headOff = (size_t)h * 64;

    auto gaddr = [&](const hf* base, int srow, int cu) {
        return base + ((size_t)(b * CS + srow) * CD + headOff + (cu << 3));
    };

#pragma unroll
    for (int i = 0; i < 4; i++) {
        int u = tid + i * 256, r = u >> 3, cu = u & 7;
        uint32_t d = sb + SWZ(r * 128 + cu * 16);
        CP16(d,         gaddr(Qh, qbase + r, cu));
        CP16(d + 16384, gaddr(Ql, qbase + r, cu));
    }

    auto loadKV = [&](int it, int s) {
        const uint32_t base = sb + 32768 + s * 32768;
        const int kb = it * 128;
#pragma unroll
        for (int i = 0; i < 4; i++) {
            int u = tid + i * 256, r = u >> 3, cu = u & 7;
            uint32_t sw = SWZ(r * 128 + cu * 16);
            CP16(base + sw,         gaddr(Kh, kb + r, cu));
            CP16(base + 16384 + sw, gaddr(Vh, kb + r, cu));
        }
    };

    loadKV(0, 0);
    asm volatile("cp.async.commit_group;" ::: "memory");
    loadKV(1, 1);
    asm volatile("cp.async.commit_group;" ::: "memory");

    float oacc[8][4];
#pragma unroll
    for (int i = 0; i < 8; i++)
#pragma unroll
        for (int j = 0; j < 4; j++) oacc[i][j] = 0.f;
    float m_old[2] = {-INFINITY, -INFINITY};
    float l_sum[2] = {0.f, 0.f};

    const int li = lane >> 3, lj = lane & 7;
    const int rbase = wid * 16 + (lane >> 2);

    for (int it = 0; it < 8; it++) {
        const int s = it & 1;
        if (it < 7) asm volatile("cp.async.wait_group 1;" ::: "memory");
        else        asm volatile("cp.async.wait_group 0;" ::: "memory");
        __syncthreads();

        const uint32_t kst = sb + 32768 + s * 32768;
        const uint32_t vst = kst + 16384;

        // ---- S = Q K^T (2-pass: Qh.Kh + Ql.Kh) ----
        float sacc[16][4];
#pragma unroll
        for (int i = 0; i < 16; i++)
#pragma unroll
            for (int j = 0; j < 4; j++) sacc[i][j] = 0.f;

#pragma unroll
        for (int kk = 0; kk < 4; kk++) {
            uint32_t ah[4], al[4];
            uint32_t aoff = SWZ((wid * 16 + ((li & 1) << 3) + lj) * 128 + (kk * 16 + ((li >> 1) << 3)) * 2);
            LDSM4(ah, sb + aoff);
            LDSM4(al, sb + 16384 + aoff);
            uint32_t bh[8][4];
#pragma unroll
            for (int nt = 0; nt < 8; nt++) {
                uint32_t off = SWZ((nt * 16 + ((li >> 1) << 3) + lj) * 128 + (kk * 16 + ((li & 1) << 3)) * 2);
                LDSM4(bh[nt], kst + off);
            }
#pragma unroll
            for (int nt = 0; nt < 8; nt++) { MMA(sacc[2*nt], ah, bh[nt]); MMA(sacc[2*nt+1], ah, bh[nt]+2); }
#pragma unroll
            for (int nt = 0; nt < 8; nt++) { MMA(sacc[2*nt], al, bh[nt]); MMA(sacc[2*nt+1], al, bh[nt]+2); }
        }

        // ---- mask, scale, online softmax ----
#pragma unroll
        for (int rr = 0; rr < 2; rr++) {
            const int grow = qbase + rbase + rr * 8;
            const int2* mrow = (const int2*)(mask + ((size_t)(b * CS + grow)) * CS + it * 128 + ((lane & 3) << 1));
            float mx = -INFINITY;
#pragma unroll
            for (int ni = 0; ni < 16; ni++) {
                int2 mv = mrow[ni * 4];
                float v0 = mv.x ? sacc[ni][2*rr]   * 0.125f : -1e9f;
                float v1 = mv.y ? sacc[ni][2*rr+1] * 0.125f : -1e9f;
                sacc[ni][2*rr] = v0; sacc[ni][2*rr+1] = v1;
                mx = fmaxf(mx, fmaxf(v0, v1));
            }
            mx = fmaxf(mx, __shfl_xor_sync(~0u, mx, 1));
            mx = fmaxf(mx, __shfl_xor_sync(~0u, mx, 2));
            const float mnew = fmaxf(m_old[rr], mx);
            const float scl = expf(m_old[rr] - mnew);
            float rsum = 0.f;
#pragma unroll
            for (int ni = 0; ni < 16; ni++) {
                float p0 = expf(sacc[ni][2*rr]   - mnew);
                float p1 = expf(sacc[ni][2*rr+1] - mnew);
                sacc[ni][2*rr] = p0; sacc[ni][2*rr+1] = p1;
                rsum += p0 + p1;
            }
            rsum += __shfl_xor_sync(~0u, rsum, 1);
            rsum += __shfl_xor_sync(~0u, rsum, 2);
            l_sum[rr] = l_sum[rr] * scl + rsum;
            m_old[rr] = mnew;
#pragma unroll
            for (int ni = 0; ni < 8; ni++) { oacc[ni][2*rr] *= scl; oacc[ni][2*rr+1] *= scl; }
        }

        // ---- O += P V (2-pass: Ph.Vh + Pl.Vh; V via ldmatrix.trans) ----
#pragma unroll
        for (int kk = 0; kk < 8; kk++) {
            uint32_t ah2[4], al2[4];
            const int f0 = 2 * kk, f1 = 2 * kk + 1;
            {
                __half2 h0 = __floats2half2_rn(sacc[f0][0], sacc[f0][1]);
                __half2 h1 = __floats2half2_rn(sacc[f0][2], sacc[f0][3]);
                __half2 h2 = __floats2half2_rn(sacc[f1][0], sacc[f1][1]);
                __half2 h3 = __floats2half2_rn(sacc[f1][2], sacc[f1][3]);
                ah2[0] = *reinterpret_cast<uint32_t*>(&h0);
                ah2[1] = *reinterpret_cast<uint32_t*>(&h1);
                ah2[2] = *reinterpret_cast<uint32_t*>(&h2);
                ah2[3] = *reinterpret_cast<uint32_t*>(&h3);
                al2[0] = packh2(sacc[f0][0] - __low2float(h0),  sacc[f0][1] - __high2float(h0));
                al2[1] = packh2(sacc[f0][2] - __low2float(h1),  sacc[f0][3] - __high2float(h1));
                al2[2] = packh2(sacc[f1][0] - __low2float(h2),  sacc[f1][1] - __high2float(h2));
                al2[3] = packh2(sacc[f1][2] - __low2float(h3),  sacc[f1][3] - __high2float(h3));
            }
            uint32_t vf[4][4];
#pragma unroll
            for (int nb = 0; nb < 4; nb++) {
                uint32_t off = SWZ((kk * 16 + ((li & 1) << 3) + lj) * 128 + (nb * 16 + ((li >> 1) << 3)) * 2);
                LDSM4T(vf[nb], vst + off);
            }
#pragma unroll
            for (int nb = 0; nb < 4; nb++) { MMA(oacc[2*nb], ah2, vf[nb]); MMA(oacc[2*nb+1], ah2, vf[nb]+2); }
#pragma unroll
            for (int nb = 0; nb < 4; nb++) { MMA(oacc[2*nb], al2, vf[nb]); MMA(oacc[2*nb+1], al2, vf[nb]+2); }
        }

        __syncthreads();
        if (it + 2 < 8) {
            loadKV(it + 2, s);
            asm volatile("cp.async.commit_group;" ::: "memory");
        }
    }

    // ---- normalize + split store O ----
#pragma unroll
    for (int rr = 0; rr < 2; rr++) {
        const int grow = qbase + rbase + rr * 8;
        const float inv = 1.f / l_sum[rr];
        const size_t base = (size_t)(b * CS + grow) * CD + headOff + ((lane & 3) << 1);
#pragma unroll
        for (int ni = 0; ni < 8; ni++) {
            float v0 = oacc[ni][2*rr] * inv, v1 = oacc[ni][2*rr+1] * inv;
            __half2 hp = __floats2half2_rn(v0, v1);
            __half2 lp = __floats2half2_rn(v0 - __low2float(hp), v1 - __high2float(hp));
            *reinterpret_cast<__half2*>(&Oh[base + 8 * ni]) = hp;
            *reinterpret_cast<__half2*>(&Ol[base + 8 * ni]) = lp;
        }
    }
}

// ---------------------------------------------------------------------------
// mma.sync split-fp16 GEMM: C[128 x BN] = A[128,K] . B[BN,K]^T, K = NC*64.
// A split hi/lo (2 passes), B fp16 hi only. Stage 48 KB x2 -> 2 CTA/SM.
// out: fp32 (outf) | split (outh+outl) | fp16 (outh only)
// ---------------------------------------------------------------------------
template<int BN>
__global__ __launch_bounds__(256)
void mm_gemm(const hf* __restrict__ Ah, const hf* __restrict__ Al, int lda,
             const hf* __restrict__ Bh, int ldb,
             float* __restrict__ outf, hf* __restrict__ outh, hf* __restrict__ outl, int ldc,
             const float* __restrict__ bias, const float* __restrict__ res,
             int gelu, int NC)
{
    constexpr int NF  = BN / 16;
    constexpr int ASZ = 128 * 128;
    constexpr int BSZ = BN * 128;
    constexpr int STG = 2 * ASZ + BSZ;

    extern __shared__ char smem[];
    const uint32_t sb = (uint32_t)__cvta_generic_to_shared(smem);
    const int tid = threadIdx.x, wid = tid >> 5, lane = tid & 31;
    const int bm = blockIdx.y * 128, bn = blockIdx.x * BN;

    const int wm = (wid & 3) * 32;
    const int wn = (wid >> 2) * (BN / 2);

    auto load_chunk = [&](int c, int s) {
        const uint32_t base = sb + s * STG;
        const int k0 = c * 64;
#pragma unroll
        for (int i = 0; i < 4; i++) {
            int u = tid + i * 256, r = u >> 3, cu = u & 7;
            uint32_t d = base + SWZ(r * 128 + cu * 16);
            size_t g = (size_t)(bm + r) * lda + k0 + cu * 8;
            CP16(d,       Ah + g);
            CP16(d + ASZ, Al + g);
        }
#pragma unroll
        for (int i = 0; i < BN / 32; i++) {
            int u = tid + i * 256, r = u >> 3, cu = u & 7;
            uint32_t d = base + 2 * ASZ + SWZ(r * 128 + cu * 16);
            CP16(d, Bh + (size_t)(bn + r) * ldb + k0 + cu * 8);
        }
    };

    float acc[2][NF][4];
#pragma unroll
    for (int mi = 0; mi < 2; mi++)
#pragma unroll
        for (int ni = 0; ni < NF; ni++)
#pragma unroll
            for (int cc = 0; cc < 4; cc++) acc[mi][ni][cc] = 0.f;

    load_chunk(0, 0);
    asm volatile("cp.async.commit_group;" ::: "memory");

    const int li = lane >> 3, lj = lane & 7;

    for (int c = 0; c < NC; c++) {
        const int s = c & 1;
        if (c + 1 < NC) {
            load_chunk(c + 1, (c + 1) & 1);
            asm volatile("cp.async.commit_group;" ::: "memory");
            asm volatile("cp.async.wait_group 1;" ::: "memory");
        } else {
            asm volatile("cp.async.wait_group 0;" ::: "memory");
        }
        __syncthreads();

        const uint32_t aBase = sb + s * STG;
        const uint32_t bBase = aBase + 2 * ASZ;

#pragma unroll
        for (int ks = 0; ks < 4; ks++) {
            const int kb = ks * 16;
            uint32_t ah[2][4], al[2][4];
#pragma unroll
            for (int mi = 0; mi < 2; mi++) {
                int row = wm + mi * 16 + ((li & 1) << 3) + lj;
                int col = kb + ((li >> 1) << 3);
                uint32_t off = SWZ(row * 128 + col * 2);
                LDSM4(ah[mi], aBase + off);
                LDSM4(al[mi], aBase + ASZ + off);
            }
            uint32_t bh[NF][2];
#pragma unroll
            for (int nt = 0; nt < NF / 2; nt++) {
                int row = wn + nt * 16 + ((li >> 1) << 3) + lj;
                int col = kb + ((li & 1) << 3);
                uint32_t r4[4];
                LDSM4(r4, bBase + SWZ(row * 128 + col * 2));
                bh[2*nt][0] = r4[0]; bh[2*nt][1] = r4[1];
                bh[2*nt+1][0] = r4[2]; bh[2*nt+1][1] = r4[3];
            }
#pragma unroll
            for (int mi = 0; mi < 2; mi++)
#pragma unroll
                for (int ni = 0; ni < NF; ni++) MMA(acc[mi][ni], ah[mi], bh[ni]);
#pragma unroll
            for (int mi = 0; mi < 2; mi++)
#pragma unroll
                for (int ni = 0; ni < NF; ni++) MMA(acc[mi][ni], al[mi], bh[ni]);
        }
        __syncthreads();
    }

#pragma unroll
    for (int mi = 0; mi < 2; mi++) {
#pragma unroll
        for (int ni = 0; ni < NF; ni++) {
            const int m0 = bm + wm + mi * 16 + (lane >> 2);
            const int n0 = bn + wn + ni * 8 + ((lane & 3) << 1);
#pragma unroll
            for (int rr = 0; rr < 2; rr++) {
                const int m = m0 + rr * 8;
                float v0 = acc[mi][ni][2*rr + 0];
                float v1 = acc[mi][ni][2*rr + 1];
                if (bias) { v0 += bias[n0]; v1 += bias[n0 + 1]; }
                if (gelu) { v0 = gelu_f(v0); v1 = gelu_f(v1); }
                size_t idx = (size_t)m * ldc + n0;
                if (res) { v0 += res[idx]; v1 += res[idx + 1]; }
                if (outf) {
                    outf[idx] = v0; outf[idx + 1] = v1;
                } else if (outl) {
                    __half2 hp = __floats2half2_rn(v0, v1);
                    __half2 lp = __floats2half2_rn(v0 - __low2float(hp), v1 - __high2float(hp));
                    *reinterpret_cast<__half2*>(&outh[idx]) = hp;
                    *reinterpret_cast<__half2*>(&outl[idx]) = lp;
                } else {
                    *reinterpret_cast<__half2*>(&outh[idx]) = __floats2half2_rn(v0, v1);
                }
            }
        }
    }
}

// ---------------------------------------------------------------------------
extern "C" void kernel_launch(void* const* d_in, const int* in_sizes, int n_in,
                              void* d_out, int out_size)
{
    const float* x    = (const float*)d_in[0];
    const int*   mask = (const int*)  d_in[1];
    const float* wq = (const float*)d_in[2],  *bq = (const float*)d_in[3];
    const float* wk = (const float*)d_in[4],  *bk = (const float*)d_in[5];
    const float* wv = (const float*)d_in[6],  *bv = (const float*)d_in[7];
    const float* wo = (const float*)d_in[8],  *bo = (const float*)d_in[9];
    const float* w1 = (const float*)d_in[10], *b1 = (const float*)d_in[11];
    const float* w2 = (const float*)d_in[12], *b2 = (const float*)d_in[13];
    const float* g1 = (const float*)d_in[14], *be1 = (const float*)d_in[15];
    const float* g2 = (const float*)d_in[16], *be2 = (const float*)d_in[17];
    float* out = (float*)d_out;

    hf *xnh,*xnl,*qh,*ql,*kh,*vh,*oh,*ol,*h1h,*h1l;
    hf *wqc,*wkc,*wvc,*woc,*w1c,*w2c;
    cudaGetSymbolAddress((void**)&xnh, g_xnh); cudaGetSymbolAddress((void**)&xnl, g_xnl);
    cudaGetSymbolAddress((void**)&qh, g_qh);   cudaGetSymbolAddress((void**)&ql, g_ql);
    cudaGetSymbolAddress((void**)&kh, g_kh);   cudaGetSymbolAddress((void**)&vh, g_vh);
    cudaGetSymbolAddress((void**)&oh, g_oh);   cudaGetSymbolAddress((void**)&ol, g_ol);
    cudaGetSymbolAddress((void**)&h1h, g_h1h); cudaGetSymbolAddress((void**)&h1l, g_h1l);
    cudaGetSymbolAddress((void**)&wqc, g_wq);  cudaGetSymbolAddress((void**)&wkc, g_wk);
    cudaGetSymbolAddress((void**)&wvc, g_wv);  cudaGetSymbolAddress((void**)&woc, g_wo);
    cudaGetSymbolAddress((void**)&w1c, g_w1);  cudaGetSymbolAddress((void**)&w2c, g_w2);

    const int SM128 = 2 * (2 * 16384 + 16384);   // 98304
    const int SMFL  = 32768 + 2 * 32768;         // 98304
    cudaFuncSetAttribute(mm_gemm<128>, cudaFuncAttributeMaxDynamicSharedMemorySize, SM128);
    cudaFuncSetAttribute(flash_kernel, cudaFuncAttributeMaxDynamicSharedMemorySize, SMFL);

    // weight conversions (fp16, hi only)
    conv_kernel<<<4096, 256>>>(wq, wqc, CD * CD);
    conv_kernel<<<4096, 256>>>(wk, wkc, CD * CD);
    conv_kernel<<<4096, 256>>>(wv, wvc, CD * CD);
    conv_kernel<<<4096, 256>>>(wo, woc, CD * CD);
    conv_kernel<<<16384, 256>>>(w1, w1c, CDFF * CD);
    conv_kernel<<<16384, 256>>>(w2, w2c, CD * CDFF);

    // LN1 -> xn (split)
    ln_split_kernel<<<NTOK, 256>>>(x, g1, be1, xnh, xnl);

    // QKV projections: Q split, K/V fp16
    dim3 gD(CD / 128, NTOK / 128);
    mm_gemm<128><<<gD, 256, SM128>>>(xnh, xnl, CD, wqc, CD,
        nullptr, qh, ql, CD, bq, nullptr, 0, 16);
    mm_gemm<128><<<gD, 256, SM128>>>(xnh, xnl, CD, wkc, CD,
        nullptr, kh, nullptr, CD, bk, nullptr, 0, 16);
    mm_gemm<128><<<gD, 256, SM128>>>(xnh, xnl, CD, wvc, CD,
        nullptr, vh, nullptr, CD, bv, nullptr, 0, 16);

    // fused attention -> O (split)
    dim3 gA(CS / 128, CB * CH);
    flash_kernel<<<gA, 256, SMFL>>>(qh, ql, kh, vh, mask, oh, ol);

    // x1 = O wo^T + bo + x -> out (fp32)
    mm_gemm<128><<<gD, 256, SM128>>>(oh, ol, CD, woc, CD,
        out, nullptr, nullptr, CD, bo, x, 0, 16);

    // LN2 -> xn (split)
    ln_split_kernel<<<NTOK, 256>>>(out, g2, be2, xnh, xnl);

    // h1 = gelu(xn w1^T + b1) (split)
    dim3 gF(CDFF / 128, NTOK / 128);
    mm_gemm<128><<<gF, 256, SM128>>>(xnh, xnl, CD, w1c, CD,
        nullptr, h1h, h1l, CDFF, b1, nullptr, 1, 16);

    // out = x1 + h1 w2^T + b2
    mm_gemm<128><<<gD, 256, SM128>>>(h1h, h1l, CDFF, w2c, CDFF,
        out, nullptr, nullptr, CD, b2, out, 0, 64);
}

// round 7
// speedup vs baseline: 5.9188x; 1.3881x over previous
#include <cuda_runtime.h>
#include <cuda_fp16.h>
#include <math.h>
#include <stdint.h>

#define CB 8
#define CS 1024
#define CD 1024
#define CH 16
#define CDK 64
#define CDFF 4096
#define NTOK (CB*CS)
typedef __half hf;

#define SWZ(o) ((o) ^ (((o) >> 3) & 0x70))
#define CP16(dst, src) asm volatile("cp.async.cg.shared.global [%0], [%1], 16;" :: "r"(dst), "l"(src) : "memory")

#define LDSM4(r, a) \
    asm volatile("ldmatrix.sync.aligned.m8n8.x4.shared.b16 {%0,%1,%2,%3}, [%4];" \
        : "=r"((r)[0]), "=r"((r)[1]), "=r"((r)[2]), "=r"((r)[3]) : "r"(a))
#define LDSM4T(r, a) \
    asm volatile("ldmatrix.sync.aligned.m8n8.x4.trans.shared.b16 {%0,%1,%2,%3}, [%4];" \
        : "=r"((r)[0]), "=r"((r)[1]), "=r"((r)[2]), "=r"((r)[3]) : "r"(a))

#define MMA(c, a, b) \
    asm volatile("mma.sync.aligned.m16n8k16.row.col.f32.f16.f16.f32 " \
        "{%0,%1,%2,%3},{%4,%5,%6,%7},{%8,%9},{%0,%1,%2,%3};" \
        : "+f"((c)[0]), "+f"((c)[1]), "+f"((c)[2]), "+f"((c)[3]) \
        : "r"((a)[0]), "r"((a)[1]), "r"((a)[2]), "r"((a)[3]), "r"((b)[0]), "r"((b)[1]))

__device__ __forceinline__ float gelu_f(float x) {
    float x3 = x * x * x;
    return 0.5f * x * (1.0f + tanhf(0.7978845608028654f * (x + 0.044715f * x3)));
}
__device__ __forceinline__ void split_store(float v, hf* h, hf* l, size_t i) {
    hf hi = __float2half_rn(v);
    h[i] = hi;
    l[i] = __float2half_rn(v - __half2float(hi));
}
__device__ __forceinline__ uint32_t packh2(float a, float b) {
    __half2 t = __floats2half2_rn(a, b);
    return *reinterpret_cast<uint32_t*>(&t);
}

// ------------------------- scratch -------------------------
__device__ hf g_xnh[NTOK*CD], g_xnl[NTOK*CD];
__device__ hf g_qh[NTOK*CD],  g_ql[NTOK*CD];
__device__ hf g_kh[NTOK*CD];
__device__ hf g_vh[NTOK*CD];
__device__ hf g_oh[NTOK*CD];
__device__ hf g_h1h[(size_t)NTOK*CDFF];
__device__ hf g_wq[CD*CD], g_wk[CD*CD], g_wv[CD*CD], g_wo[CD*CD];
__device__ hf g_w1[(size_t)CDFF*CD], g_w2[(size_t)CD*CDFF];

__global__ __launch_bounds__(256)
void conv_kernel(const float* __restrict__ w, hf* __restrict__ h, int n4) {
    int i = blockIdx.x * 256 + threadIdx.x;
    if (i < n4) {
        float4 v = reinterpret_cast<const float4*>(w)[i];
        __half2 a = __floats2half2_rn(v.x, v.y);
        __half2 b = __floats2half2_rn(v.z, v.w);
        reinterpret_cast<__half2*>(h)[2*i]   = a;
        reinterpret_cast<__half2*>(h)[2*i+1] = b;
    }
}

// ------------------------- LayerNorm (ddof=1, eps on std) -> fp16 (opt split) ---------------
__global__ __launch_bounds__(256)
void ln_split_kernel(const float* __restrict__ x, const float* __restrict__ gamma,
                     const float* __restrict__ beta, hf* __restrict__ oh, hf* __restrict__ ol) {
    const int row = blockIdx.x;
    const float* xr = x + (size_t)row * CD;
    const int t = threadIdx.x;
    float v[4];
#pragma unroll
    for (int i = 0; i < 4; i++) v[i] = xr[t + 256 * i];
    __shared__ float red[8];
    __shared__ float s_mean, s_rstd;
    float s = v[0] + v[1] + v[2] + v[3];
#pragma unroll
    for (int o = 16; o > 0; o >>= 1) s += __shfl_xor_sync(~0u, s, o);
    if ((t & 31) == 0) red[t >> 5] = s;
    __syncthreads();
    if (t < 8) {
        float r = red[t];
#pragma unroll
        for (int o = 4; o > 0; o >>= 1) r += __shfl_xor_sync(0xffu, r, o);
        if (t == 0) s_mean = r * (1.0f / CD);
    }
    __syncthreads();
    const float mean = s_mean;
    float q = 0.f;
#pragma unroll
    for (int i = 0; i < 4; i++) { float d = v[i] - mean; q += d * d; }
#pragma unroll
    for (int o = 16; o > 0; o >>= 1) q += __shfl_xor_sync(~0u, q, o);
    if ((t & 31) == 0) red[t >> 5] = q;
    __syncthreads();
    if (t < 8) {
        float r = red[t];
#pragma unroll
        for (int o = 4; o > 0; o >>= 1) r += __shfl_xor_sync(0xffu, r, o);
        if (t == 0) s_rstd = 1.0f / (sqrtf(r * (1.0f / (CD - 1))) + 1e-5f);
    }
    __syncthreads();
    const float rstd = s_rstd;
#pragma unroll
    for (int i = 0; i < 4; i++) {
        int c = t + 256 * i;
        float y = gamma[c] * (v[i] - mean) * rstd + beta[c];
        if (ol) split_store(y, oh, ol, (size_t)row * CD + c);
        else    oh[(size_t)row * CD + c] = __float2half_rn(y);
    }
}

// ---------------------------------------------------------------------------
// Flash attention: O = softmax(mask(0.125 * Q K^T)) V.  (unchanged numerics)
// Q split hi/lo; K,V fp16. O written fp16 (hi only).
// ---------------------------------------------------------------------------
__global__ __launch_bounds__(256)
void flash_kernel(const hf* __restrict__ Qh, const hf* __restrict__ Ql,
                  const hf* __restrict__ Kh, const hf* __restrict__ Vh,
                  const int* __restrict__ mask, hf* __restrict__ Oh)
{
    extern __shared__ char smem[];
    const uint32_t sb = (uint32_t)__cvta_generic_to_shared(smem);
    const int tid = threadIdx.x, wid = tid >> 5, lane = tid & 31;
    const int qt = blockIdx.x, z = blockIdx.y;
    const int b = z >> 4, h = z & 15;
    const int qbase = qt * 128;
    const size_t headOff = (size_t)h * 64;

    auto gaddr = [&](const hf* base, int srow, int cu) {
        return base + ((size_t)(b * CS + srow) * CD + headOff + (cu << 3));
    };

#pragma unroll
    for (int i = 0; i < 4; i++) {
        int u = tid + i * 256, r = u >> 3, cu = u & 7;
        uint32_t d = sb + SWZ(r * 128 + cu * 16);
        CP16(d,         gaddr(Qh, qbase + r, cu));
        CP16(d + 16384, gaddr(Ql, qbase + r, cu));
    }

    auto loadKV = [&](int it, int s) {
        const uint32_t base = sb + 32768 + s * 32768;
        const int kb = it * 128;
#pragma unroll
        for (int i = 0; i < 4; i++) {
            int u = tid + i * 256, r = u >> 3, cu = u & 7;
            uint32_t sw = SWZ(r * 128 + cu * 16);
            CP16(base + sw,         gaddr(Kh, kb + r, cu));
            CP16(base + 16384 + sw, gaddr(Vh, kb + r, cu));
        }
    };

    loadKV(0, 0);
    asm volatile("cp.async.commit_group;" ::: "memory");
    loadKV(1, 1);
    asm volatile("cp.async.commit_group;" ::: "memory");

    float oacc[8][4];
#pragma unroll
    for (int i = 0; i < 8; i++)
#pragma unroll
        for (int j = 0; j < 4; j++) oacc[i][j] = 0.f;
    float m_old[2] = {-INFINITY, -INFINITY};
    float l_sum[2] = {0.f, 0.f};

    const int li = lane >> 3, lj = lane & 7;
    const int rbase = wid * 16 + (lane >> 2);

    for (int it = 0; it < 8; it++) {
        const int s = it & 1;
        if (it < 7) asm volatile("cp.async.wait_group 1;" ::: "memory");
        else        asm volatile("cp.async.wait_group 0;" ::: "memory");
        __syncthreads();

        const uint32_t kst = sb + 32768 + s * 32768;
        const uint32_t vst = kst + 16384;

        float sacc[16][4];
#pragma unroll
        for (int i = 0; i < 16; i++)
#pragma unroll
            for (int j = 0; j < 4; j++) sacc[i][j] = 0.f;

#pragma unroll
        for (int kk = 0; kk < 4; kk++) {
            uint32_t ah[4], al[4];
            uint32_t aoff = SWZ((wid * 16 + ((li & 1) << 3) + lj) * 128 + (kk * 16 + ((li >> 1) << 3)) * 2);
            LDSM4(ah, sb + aoff);
            LDSM4(al, sb + 16384 + aoff);
            uint32_t bh[8][4];
#pragma unroll
            for (int nt = 0; nt < 8; nt++) {
                uint32_t off = SWZ((nt * 16 + ((li >> 1) << 3) + lj) * 128 + (kk * 16 + ((li & 1) << 3)) * 2);
                LDSM4(bh[nt], kst + off);
            }
#pragma unroll
            for (int nt = 0; nt < 8; nt++) { MMA(sacc[2*nt], ah, bh[nt]); MMA(sacc[2*nt+1], ah, bh[nt]+2); }
#pragma unroll
            for (int nt = 0; nt < 8; nt++) { MMA(sacc[2*nt], al, bh[nt]); MMA(sacc[2*nt+1], al, bh[nt]+2); }
        }

#pragma unroll
        for (int rr = 0; rr < 2; rr++) {
            const int grow = qbase + rbase + rr * 8;
            const int2* mrow = (const int2*)(mask + ((size_t)(b * CS + grow)) * CS + it * 128 + ((lane & 3) << 1));
            float mx = -INFINITY;
#pragma unroll
            for (int ni = 0; ni < 16; ni++) {
                int2 mv = mrow[ni * 4];
                float v0 = mv.x ? sacc[ni][2*rr]   * 0.125f : -1e9f;
                float v1 = mv.y ? sacc[ni][2*rr+1] * 0.125f : -1e9f;
                sacc[ni][2*rr] = v0; sacc[ni][2*rr+1] = v1;
                mx = fmaxf(mx, fmaxf(v0, v1));
            }
            mx = fmaxf(mx, __shfl_xor_sync(~0u, mx, 1));
            mx = fmaxf(mx, __shfl_xor_sync(~0u, mx, 2));
            const float mnew = fmaxf(m_old[rr], mx);
            const float scl = expf(m_old[rr] - mnew);
            float rsum = 0.f;
#pragma unroll
            for (int ni = 0; ni < 16; ni++) {
                float p0 = expf(sacc[ni][2*rr]   - mnew);
                float p1 = expf(sacc[ni][2*rr+1] - mnew);
                sacc[ni][2*rr] = p0; sacc[ni][2*rr+1] = p1;
                rsum += p0 + p1;
            }
            rsum += __shfl_xor_sync(~0u, rsum, 1);
            rsum += __shfl_xor_sync(~0u, rsum, 2);
            l_sum[rr] = l_sum[rr] * scl + rsum;
            m_old[rr] = mnew;
#pragma unroll
            for (int ni = 0; ni < 8; ni++) { oacc[ni][2*rr] *= scl; oacc[ni][2*rr+1] *= scl; }
        }

#pragma unroll
        for (int kk = 0; kk < 8; kk++) {
            uint32_t ah2[4], al2[4];
            const int f0 = 2 * kk, f1 = 2 * kk + 1;
            {
                __half2 h0 = __floats2half2_rn(sacc[f0][0], sacc[f0][1]);
                __half2 h1 = __floats2half2_rn(sacc[f0][2], sacc[f0][3]);
                __half2 h2 = __floats2half2_rn(sacc[f1][0], sacc[f1][1]);
                __half2 h3 = __floats2half2_rn(sacc[f1][2], sacc[f1][3]);
                ah2[0] = *reinterpret_cast<uint32_t*>(&h0);
                ah2[1] = *reinterpret_cast<uint32_t*>(&h1);
                ah2[2] = *reinterpret_cast<uint32_t*>(&h2);
                ah2[3] = *reinterpret_cast<uint32_t*>(&h3);
                al2[0] = packh2(sacc[f0][0] - __low2float(h0),  sacc[f0][1] - __high2float(h0));
                al2[1] = packh2(sacc[f0][2] - __low2float(h1),  sacc[f0][3] - __high2float(h1));
                al2[2] = packh2(sacc[f1][0] - __low2float(h2),  sacc[f1][1] - __high2float(h2));
                al2[3] = packh2(sacc[f1][2] - __low2float(h3),  sacc[f1][3] - __high2float(h3));
            }
            uint32_t vf[4][4];
#pragma unroll
            for (int nb = 0; nb < 4; nb++) {
                uint32_t off = SWZ((kk * 16 + ((li & 1) << 3) + lj) * 128 + (nb * 16 + ((li >> 1) << 3)) * 2);
                LDSM4T(vf[nb], vst + off);
            }
#pragma unroll
            for (int nb = 0; nb < 4; nb++) { MMA(oacc[2*nb], ah2, vf[nb]); MMA(oacc[2*nb+1], ah2, vf[nb]+2); }
#pragma unroll
            for (int nb = 0; nb < 4; nb++) { MMA(oacc[2*nb], al2, vf[nb]); MMA(oacc[2*nb+1], al2, vf[nb]+2); }
        }

        __syncthreads();
        if (it + 2 < 8) {
            loadKV(it + 2, s);
            asm volatile("cp.async.commit_group;" ::: "memory");
        }
    }

#pragma unroll
    for (int rr = 0; rr < 2; rr++) {
        const int grow = qbase + rbase + rr * 8;
        const float inv = 1.f / l_sum[rr];
        const size_t base = (size_t)(b * CS + grow) * CD + headOff + ((lane & 3) << 1);
#pragma unroll
        for (int ni = 0; ni < 8; ni++) {
            float v0 = oacc[ni][2*rr] * inv, v1 = oacc[ni][2*rr+1] * inv;
            *reinterpret_cast<__half2*>(&Oh[base + 8 * ni]) = __floats2half2_rn(v0, v1);
        }
    }
}

// ---------------------------------------------------------------------------
// mma.sync fp16 GEMM: C[128 x BN] = A[128,K] . B[BN,K]^T, K = NC*64.
// SPLITA: A hi+lo, 2 MMA passes; else pure fp16 1 pass.
// ---------------------------------------------------------------------------
template<int BN, bool SPLITA>
__global__ __launch_bounds__(256)
void mm_gemm(const hf* __restrict__ Ah, const hf* __restrict__ Al, int lda,
             const hf* __restrict__ Bh, int ldb,
             float* __restrict__ outf, hf* __restrict__ outh, hf* __restrict__ outl, int ldc,
             const float* __restrict__ bias, const float* __restrict__ res,
             int gelu, int NC)
{
    constexpr int NF  = BN / 16;
    constexpr int ASZ = 128 * 128;
    constexpr int BSZ = BN * 128;
    constexpr int NA  = SPLITA ? 2 : 1;
    constexpr int STG = NA * ASZ + BSZ;

    extern __shared__ char smem[];
    const uint32_t sb = (uint32_t)__cvta_generic_to_shared(smem);
    const int tid = threadIdx.x, wid = tid >> 5, lane = tid & 31;
    const int bm = blockIdx.y * 128, bn = blockIdx.x * BN;

    const int wm = (wid & 3) * 32;
    const int wn = (wid >> 2) * (BN / 2);

    auto load_chunk = [&](int c, int s) {
        const uint32_t base = sb + s * STG;
        const int k0 = c * 64;
#pragma unroll
        for (int i = 0; i < 4; i++) {
            int u = tid + i * 256, r = u >> 3, cu = u & 7;
            uint32_t d = base + SWZ(r * 128 + cu * 16);
            size_t g = (size_t)(bm + r) * lda + k0 + cu * 8;
            CP16(d, Ah + g);
            if (SPLITA) CP16(d + ASZ, Al + g);
        }
#pragma unroll
        for (int i = 0; i < BN / 32; i++) {
            int u = tid + i * 256, r = u >> 3, cu = u & 7;
            uint32_t d = base + NA * ASZ + SWZ(r * 128 + cu * 16);
            CP16(d, Bh + (size_t)(bn + r) * ldb + k0 + cu * 8);
        }
    };

    float acc[2][NF][4];
#pragma unroll
    for (int mi = 0; mi < 2; mi++)
#pragma unroll
        for (int ni = 0; ni < NF; ni++)
#pragma unroll
            for (int cc = 0; cc < 4; cc++) acc[mi][ni][cc] = 0.f;

    load_chunk(0, 0);
    asm volatile("cp.async.commit_group;" ::: "memory");

    const int li = lane >> 3, lj = lane & 7;

    for (int c = 0; c < NC; c++) {
        const int s = c & 1;
        if (c + 1 < NC) {
            load_chunk(c + 1, (c + 1) & 1);
            asm volatile("cp.async.commit_group;" ::: "memory");
            asm volatile("cp.async.wait_group 1;" ::: "memory");
        } else {
            asm volatile("cp.async.wait_group 0;" ::: "memory");
        }
        __syncthreads();

        const uint32_t aBase = sb + s * STG;
        const uint32_t bBase = aBase + NA * ASZ;

#pragma unroll
        for (int ks = 0; ks < 4; ks++) {
            const int kb = ks * 16;
            uint32_t ah[2][4], al[2][4];
#pragma unroll
            for (int mi = 0; mi < 2; mi++) {
                int row = wm + mi * 16 + ((li & 1) << 3) + lj;
                int col = kb + ((li >> 1) << 3);
                uint32_t off = SWZ(row * 128 + col * 2);
                LDSM4(ah[mi], aBase + off);
                if (SPLITA) LDSM4(al[mi], aBase + ASZ + off);
            }
            uint32_t bh[NF][2];
#pragma unroll
            for (int nt = 0; nt < NF / 2; nt++) {
                int row = wn + nt * 16 + ((li >> 1) << 3) + lj;
                int col = kb + ((li & 1) << 3);
                uint32_t r4[4];
                LDSM4(r4, bBase + SWZ(row * 128 + col * 2));
                bh[2*nt][0] = r4[0]; bh[2*nt][1] = r4[1];
                bh[2*nt+1][0] = r4[2]; bh[2*nt+1][1] = r4[3];
            }
#pragma unroll
            for (int mi = 0; mi < 2; mi++)
#pragma unroll
                for (int ni = 0; ni < NF; ni++) MMA(acc[mi][ni], ah[mi], bh[ni]);
            if (SPLITA) {
#pragma unroll
                for (int mi = 0; mi < 2; mi++)
#pragma unroll
                    for (int ni = 0; ni < NF; ni++) MMA(acc[mi][ni], al[mi], bh[ni]);
            }
        }
        __syncthreads();
    }

#pragma unroll
    for (int mi = 0; mi < 2; mi++) {
#pragma unroll
        for (int ni = 0; ni < NF; ni++) {
            const int m0 = bm + wm + mi * 16 + (lane >> 2);
            const int n0 = bn + wn + ni * 8 + ((lane & 3) << 1);
#pragma unroll
            for (int rr = 0; rr < 2; rr++) {
                const int m = m0 + rr * 8;
                float v0 = acc[mi][ni][2*rr + 0];
                float v1 = acc[mi][ni][2*rr + 1];
                if (bias) { v0 += bias[n0]; v1 += bias[n0 + 1]; }
                if (gelu) { v0 = gelu_f(v0); v1 = gelu_f(v1); }
                size_t idx = (size_t)m * ldc + n0;
                if (res) { v0 += res[idx]; v1 += res[idx + 1]; }
                if (outf) {
                    outf[idx] = v0; outf[idx + 1] = v1;
                } else if (outl) {
                    __half2 hp = __floats2half2_rn(v0, v1);
                    __half2 lp = __floats2half2_rn(v0 - __low2float(hp), v1 - __high2float(hp));
                    *reinterpret_cast<__half2*>(&outh[idx]) = hp;
                    *reinterpret_cast<__half2*>(&outl[idx]) = lp;
                } else {
                    *reinterpret_cast<__half2*>(&outh[idx]) = __floats2half2_rn(v0, v1);
                }
            }
        }
    }
}

// ---------------------------------------------------------------------------
extern "C" void kernel_launch(void* const* d_in, const int* in_sizes, int n_in,
                              void* d_out, int out_size)
{
    const float* x    = (const float*)d_in[0];
    const int*   mask = (const int*)  d_in[1];
    const float* wq = (const float*)d_in[2],  *bq = (const float*)d_in[3];
    const float* wk = (const float*)d_in[4],  *bk = (const float*)d_in[5];
    const float* wv = (const float*)d_in[6],  *bv = (const float*)d_in[7];
    const float* wo = (const float*)d_in[8],  *bo = (const float*)d_in[9];
    const float* w1 = (const float*)d_in[10], *b1 = (const float*)d_in[11];
    const float* w2 = (const float*)d_in[12], *b2 = (const float*)d_in[13];
    const float* g1 = (const float*)d_in[14], *be1 = (const float*)d_in[15];
    const float* g2 = (const float*)d_in[16], *be2 = (const float*)d_in[17];
    float* out = (float*)d_out;

    hf *xnh,*xnl,*qh,*ql,*kh,*vh,*oh,*h1h;
    hf *wqc,*wkc,*wvc,*woc,*w1c,*w2c;
    cudaGetSymbolAddress((void**)&xnh, g_xnh); cudaGetSymbolAddress((void**)&xnl, g_xnl);
    cudaGetSymbolAddress((void**)&qh, g_qh);   cudaGetSymbolAddress((void**)&ql, g_ql);
    cudaGetSymbolAddress((void**)&kh, g_kh);   cudaGetSymbolAddress((void**)&vh, g_vh);
    cudaGetSymbolAddress((void**)&oh, g_oh);   cudaGetSymbolAddress((void**)&h1h, g_h1h);
    cudaGetSymbolAddress((void**)&wqc, g_wq);  cudaGetSymbolAddress((void**)&wkc, g_wk);
    cudaGetSymbolAddress((void**)&wvc, g_wv);  cudaGetSymbolAddress((void**)&woc, g_wo);
    cudaGetSymbolAddress((void**)&w1c, g_w1);  cudaGetSymbolAddress((void**)&w2c, g_w2);

    const int SMSPL = 2 * (2 * 16384 + 16384);   // 98304 (split-A)
    const int SMONE = 2 * (16384 + 16384);       // 65536 (fp16-A)
    const int SMFL  = 32768 + 2 * 32768;         // 98304
    cudaFuncSetAttribute((const void*)mm_gemm<128,true>,  cudaFuncAttributeMaxDynamicSharedMemorySize, SMSPL);
    cudaFuncSetAttribute((const void*)mm_gemm<128,false>, cudaFuncAttributeMaxDynamicSharedMemorySize, SMONE);
    cudaFuncSetAttribute((const void*)flash_kernel, cudaFuncAttributeMaxDynamicSharedMemorySize, SMFL);

    // weight conversions (fp16)
    conv_kernel<<<1024, 256>>>(wq, wqc, CD * CD / 4);
    conv_kernel<<<1024, 256>>>(wk, wkc, CD * CD / 4);
    conv_kernel<<<1024, 256>>>(wv, wvc, CD * CD / 4);
    conv_kernel<<<1024, 256>>>(wo, woc, CD * CD / 4);
    conv_kernel<<<4096, 256>>>(w1, w1c, CDFF * CD / 4);
    conv_kernel<<<4096, 256>>>(w2, w2c, CD * CDFF / 4);

    // LN1 -> xn (split: QKV projections are 2-pass)
    ln_split_kernel<<<NTOK, 256>>>(x, g1, be1, xnh, xnl);

    // QKV projections (split-A): Q split out, K/V fp16 out
    dim3 gD(CD / 128, NTOK / 128);
    mm_gemm<128,true><<<gD, 256, SMSPL>>>(xnh, xnl, CD, wqc, CD,
        nullptr, qh, ql, CD, bq, nullptr, 0, 16);
    mm_gemm<128,true><<<gD, 256, SMSPL>>>(xnh, xnl, CD, wkc, CD,
        nullptr, kh, nullptr, CD, bk, nullptr, 0, 16);
    mm_gemm<128,true><<<gD, 256, SMSPL>>>(xnh, xnl, CD, wvc, CD,
        nullptr, vh, nullptr, CD, bv, nullptr, 0, 16);

    // fused attention -> O (fp16)
    dim3 gA(CS / 128, CB * CH);
    flash_kernel<<<gA, 256, SMFL>>>(qh, ql, kh, vh, mask, oh);

    // x1 = O wo^T + bo + x -> out (fp32), 1-pass
    mm_gemm<128,false><<<gD, 256, SMONE>>>(oh, nullptr, CD, woc, CD,
        out, nullptr, nullptr, CD, bo, x, 0, 16);

    // LN2 -> xn (hi only: FFN1 is 1-pass)
    ln_split_kernel<<<NTOK, 256>>>(out, g2, be2, xnh, nullptr);

    // h1 = gelu(xn w1^T + b1) (fp16), 1-pass
    dim3 gF(CDFF / 128, NTOK / 128);
    mm_gemm<128,false><<<gF, 256, SMONE>>>(xnh, nullptr, CD, w1c, CD,
        nullptr, h1h, nullptr, CDFF, b1, nullptr, 1, 16);

    // out = x1 + h1 w2^T + b2, 1-pass
    mm_gemm<128,false><<<gD, 256, SMONE>>>(h1h, nullptr, CDFF, w2c, CDFF,
        out, nullptr, nullptr, CD, b2, out, 0, 64);
}

// round 8
// speedup vs baseline: 6.8079x; 1.1502x over previous
#include <cuda_runtime.h>
#include <cuda_fp16.h>
#include <math.h>
#include <stdint.h>

#define CB 8
#define CS 1024
#define CD 1024
#define CH 16
#define CDK 64
#define CDFF 4096
#define NTOK (CB*CS)
typedef __half hf;

#define SWZ(o) ((o) ^ (((o) >> 3) & 0x70))
#define CP16(dst, src) asm volatile("cp.async.cg.shared.global [%0], [%1], 16;" :: "r"(dst), "l"(src) : "memory")

#define LDSM4(r, a) \
    asm volatile("ldmatrix.sync.aligned.m8n8.x4.shared.b16 {%0,%1,%2,%3}, [%4];" \
        : "=r"((r)[0]), "=r"((r)[1]), "=r"((r)[2]), "=r"((r)[3]) : "r"(a))
#define LDSM4T(r, a) \
    asm volatile("ldmatrix.sync.aligned.m8n8.x4.trans.shared.b16 {%0,%1,%2,%3}, [%4];" \
        : "=r"((r)[0]), "=r"((r)[1]), "=r"((r)[2]), "=r"((r)[3]) : "r"(a))

#define MMA(c, a, b) \
    asm volatile("mma.sync.aligned.m16n8k16.row.col.f32.f16.f16.f32 " \
        "{%0,%1,%2,%3},{%4,%5,%6,%7},{%8,%9},{%0,%1,%2,%3};" \
        : "+f"((c)[0]), "+f"((c)[1]), "+f"((c)[2]), "+f"((c)[3]) \
        : "r"((a)[0]), "r"((a)[1]), "r"((a)[2]), "r"((a)[3]), "r"((b)[0]), "r"((b)[1]))

__device__ __forceinline__ float gelu_f(float x) {
    float x3 = x * x * x;
    return 0.5f * x * (1.0f + tanhf(0.7978845608028654f * (x + 0.044715f * x3)));
}
__device__ __forceinline__ uint32_t packh2(float a, float b) {
    __half2 t = __floats2half2_rn(a, b);
    return *reinterpret_cast<uint32_t*>(&t);
}

// ------------------------- scratch -------------------------
__device__ hf g_xnh[NTOK*CD];
__device__ hf g_qh[NTOK*CD],  g_ql[NTOK*CD];
__device__ hf g_kh[NTOK*CD];
__device__ hf g_vh[NTOK*CD];
__device__ hf g_oh[NTOK*CD];
__device__ hf g_h1h[(size_t)NTOK*CDFF];
__device__ hf g_wq[CD*CD], g_wk[CD*CD], g_wv[CD*CD], g_wo[CD*CD];
__device__ hf g_w1[(size_t)CDFF*CD], g_w2[(size_t)CD*CDFF];

__global__ __launch_bounds__(256)
void conv_kernel(const float* __restrict__ w, hf* __restrict__ h, int n4) {
    int i = blockIdx.x * 256 + threadIdx.x;
    if (i < n4) {
        float4 v = reinterpret_cast<const float4*>(w)[i];
        reinterpret_cast<__half2*>(h)[2*i]   = __floats2half2_rn(v.x, v.y);
        reinterpret_cast<__half2*>(h)[2*i+1] = __floats2half2_rn(v.z, v.w);
    }
}

// ------------------------- LayerNorm (ddof=1, eps on std) -> fp16 -------------------------
__global__ __launch_bounds__(256)
void ln_kernel(const float* __restrict__ x, const float* __restrict__ gamma,
               const float* __restrict__ beta, hf* __restrict__ oh) {
    const int row = blockIdx.x;
    const float* xr = x + (size_t)row * CD;
    const int t = threadIdx.x;
    float v[4];
#pragma unroll
    for (int i = 0; i < 4; i++) v[i] = xr[t + 256 * i];
    __shared__ float red[8];
    __shared__ float s_mean, s_rstd;
    float s = v[0] + v[1] + v[2] + v[3];
#pragma unroll
    for (int o = 16; o > 0; o >>= 1) s += __shfl_xor_sync(~0u, s, o);
    if ((t & 31) == 0) red[t >> 5] = s;
    __syncthreads();
    if (t < 8) {
        float r = red[t];
#pragma unroll
        for (int o = 4; o > 0; o >>= 1) r += __shfl_xor_sync(0xffu, r, o);
        if (t == 0) s_mean = r * (1.0f / CD);
    }
    __syncthreads();
    const float mean = s_mean;
    float q = 0.f;
#pragma unroll
    for (int i = 0; i < 4; i++) { float d = v[i] - mean; q += d * d; }
#pragma unroll
    for (int o = 16; o > 0; o >>= 1) q += __shfl_xor_sync(~0u, q, o);
    if ((t & 31) == 0) red[t >> 5] = q;
    __syncthreads();
    if (t < 8) {
        float r = red[t];
#pragma unroll
        for (int o = 4; o > 0; o >>= 1) r += __shfl_xor_sync(0xffu, r, o);
        if (t == 0) s_rstd = 1.0f / (sqrtf(r * (1.0f / (CD - 1))) + 1e-5f);
    }
    __syncthreads();
    const float rstd = s_rstd;
#pragma unroll
    for (int i = 0; i < 4; i++) {
        int c = t + 256 * i;
        oh[(size_t)row * CD + c] = __float2half_rn(gamma[c] * (v[i] - mean) * rstd + beta[c]);
    }
}

// ---------------------------------------------------------------------------
// Flash attention: O = softmax(mask(0.125 * Q K^T)) V.
// Q split hi/lo; K,V fp16. 2-pass split MMA both GEMMs. O fp16 out.
// ---------------------------------------------------------------------------
__global__ __launch_bounds__(256)
void flash_kernel(const hf* __restrict__ Qh, const hf* __restrict__ Ql,
                  const hf* __restrict__ Kh, const hf* __restrict__ Vh,
                  const int* __restrict__ mask, hf* __restrict__ Oh)
{
    extern __shared__ char smem[];
    const uint32_t sb = (uint32_t)__cvta_generic_to_shared(smem);
    const int tid = threadIdx.x, wid = tid >> 5, lane = tid & 31;
    const int qt = blockIdx.x, z = blockIdx.y;
    const int b = z >> 4, h = z & 15;
    const int qbase = qt * 128;
    const size_t headOff = (size_t)h * 64;

    auto gaddr = [&](const hf* base, int srow, int cu) {
        return base + ((size_t)(b * CS + srow) * CD + headOff + (cu << 3));
    };

#pragma unroll
    for (int i = 0; i < 4; i++) {
        int u = tid + i * 256, r = u >> 3, cu = u & 7;
        uint32_t d = sb + SWZ(r * 128 + cu * 16);
        CP16(d,         gaddr(Qh, qbase + r, cu));
        CP16(d + 16384, gaddr(Ql, qbase + r, cu));
    }

    auto loadKV = [&](int it, int s) {
        const uint32_t base = sb + 32768 + s * 32768;
        const int kb = it * 128;
#pragma unroll
        for (int i = 0; i < 4; i++) {
            int u = tid + i * 256, r = u >> 3, cu = u & 7;
            uint32_t sw = SWZ(r * 128 + cu * 16);
            CP16(base + sw,         gaddr(Kh, kb + r, cu));
            CP16(base + 16384 + sw, gaddr(Vh, kb + r, cu));
        }
    };

    loadKV(0, 0);
    asm volatile("cp.async.commit_group;" ::: "memory");
    loadKV(1, 1);
    asm volatile("cp.async.commit_group;" ::: "memory");

    float oacc[8][4];
#pragma unroll
    for (int i = 0; i < 8; i++)
#pragma unroll
        for (int j = 0; j < 4; j++) oacc[i][j] = 0.f;
    float m_old[2] = {-INFINITY, -INFINITY};
    float l_sum[2] = {0.f, 0.f};

    const int li = lane >> 3, lj = lane & 7;
    const int rbase = wid * 16 + (lane >> 2);

    for (int it = 0; it < 8; it++) {
        const int s = it & 1;
        if (it < 7) asm volatile("cp.async.wait_group 1;" ::: "memory");
        else        asm volatile("cp.async.wait_group 0;" ::: "memory");
        __syncthreads();

        const uint32_t kst = sb + 32768 + s * 32768;
        const uint32_t vst = kst + 16384;

        float sacc[16][4];
#pragma unroll
        for (int i = 0; i < 16; i++)
#pragma unroll
            for (int j = 0; j < 4; j++) sacc[i][j] = 0.f;

#pragma unroll
        for (int kk = 0; kk < 4; kk++) {
            uint32_t ah[4], al[4];
            uint32_t aoff = SWZ((wid * 16 + ((li & 1) << 3) + lj) * 128 + (kk * 16 + ((li >> 1) << 3)) * 2);
            LDSM4(ah, sb + aoff);
            LDSM4(al, sb + 16384 + aoff);
            uint32_t bh[8][4];
#pragma unroll
            for (int nt = 0; nt < 8; nt++) {
                uint32_t off = SWZ((nt * 16 + ((li >> 1) << 3) + lj) * 128 + (kk * 16 + ((li & 1) << 3)) * 2);
                LDSM4(bh[nt], kst + off);
            }
#pragma unroll
            for (int nt = 0; nt < 8; nt++) { MMA(sacc[2*nt], ah, bh[nt]); MMA(sacc[2*nt+1], ah, bh[nt]+2); }
#pragma unroll
            for (int nt = 0; nt < 8; nt++) { MMA(sacc[2*nt], al, bh[nt]); MMA(sacc[2*nt+1], al, bh[nt]+2); }
        }

#pragma unroll
        for (int rr = 0; rr < 2; rr++) {
            const int grow = qbase + rbase + rr * 8;
            const int2* mrow = (const int2*)(mask + ((size_t)(b * CS + grow)) * CS + it * 128 + ((lane & 3) << 1));
            float mx = -INFINITY;
#pragma unroll
            for (int ni = 0; ni < 16; ni++) {
                int2 mv = mrow[ni * 4];
                float v0 = mv.x ? sacc[ni][2*rr]   * 0.125f : -1e9f;
                float v1 = mv.y ? sacc[ni][2*rr+1] * 0.125f : -1e9f;
                sacc[ni][2*rr] = v0; sacc[ni][2*rr+1] = v1;
                mx = fmaxf(mx, fmaxf(v0, v1));
            }
            mx = fmaxf(mx, __shfl_xor_sync(~0u, mx, 1));
            mx = fmaxf(mx, __shfl_xor_sync(~0u, mx, 2));
            const float mnew = fmaxf(m_old[rr], mx);
            const float scl = expf(m_old[rr] - mnew);
            float rsum = 0.f;
#pragma unroll
            for (int ni = 0; ni < 16; ni++) {
                float p0 = expf(sacc[ni][2*rr]   - mnew);
                float p1 = expf(sacc[ni][2*rr+1] - mnew);
                sacc[ni][2*rr] = p0; sacc[ni][2*rr+1] = p1;
                rsum += p0 + p1;
            }
            rsum += __shfl_xor_sync(~0u, rsum, 1);
            rsum += __shfl_xor_sync(~0u, rsum, 2);
            l_sum[rr] = l_sum[rr] * scl + rsum;
            m_old[rr] = mnew;
#pragma unroll
            for (int ni = 0; ni < 8; ni++) { oacc[ni][2*rr] *= scl; oacc[ni][2*rr+1] *= scl; }
        }

#pragma unroll
        for (int kk = 0; kk < 8; kk++) {
            uint32_t ah2[4], al2[4];
            const int f0 = 2 * kk, f1 = 2 * kk + 1;
            {
                __half2 h0 = __floats2half2_rn(sacc[f0][0], sacc[f0][1]);
                __half2 h1 = __floats2half2_rn(sacc[f0][2], sacc[f0][3]);
                __half2 h2 = __floats2half2_rn(sacc[f1][0], sacc[f1][1]);
                __half2 h3 = __floats2half2_rn(sacc[f1][2], sacc[f1][3]);
                ah2[0] = *reinterpret_cast<uint32_t*>(&h0);
                ah2[1] = *reinterpret_cast<uint32_t*>(&h1);
                ah2[2] = *reinterpret_cast<uint32_t*>(&h2);
                ah2[3] = *reinterpret_cast<uint32_t*>(&h3);
                al2[0] = packh2(sacc[f0][0] - __low2float(h0),  sacc[f0][1] - __high2float(h0));
                al2[1] = packh2(sacc[f0][2] - __low2float(h1),  sacc[f0][3] - __high2float(h1));
                al2[2] = packh2(sacc[f1][0] - __low2float(h2),  sacc[f1][1] - __high2float(h2));
                al2[3] = packh2(sacc[f1][2] - __low2float(h3),  sacc[f1][3] - __high2float(h3));
            }
            uint32_t vf[4][4];
#pragma unroll
            for (int nb = 0; nb < 4; nb++) {
                uint32_t off = SWZ((kk * 16 + ((li & 1) << 3) + lj) * 128 + (nb * 16 + ((li >> 1) << 3)) * 2);
                LDSM4T(vf[nb], vst + off);
            }
#pragma unroll
            for (int nb = 0; nb < 4; nb++) { MMA(oacc[2*nb], ah2, vf[nb]); MMA(oacc[2*nb+1], ah2, vf[nb]+2); }
#pragma unroll
            for (int nb = 0; nb < 4; nb++) { MMA(oacc[2*nb], al2, vf[nb]); MMA(oacc[2*nb+1], al2, vf[nb]+2); }
        }

        __syncthreads();
        if (it + 2 < 8) {
            loadKV(it + 2, s);
            asm volatile("cp.async.commit_group;" ::: "memory");
        }
    }

#pragma unroll
    for (int rr = 0; rr < 2; rr++) {
        const int grow = qbase + rbase + rr * 8;
        const float inv = 1.f / l_sum[rr];
        const size_t base = (size_t)(b * CS + grow) * CD + headOff + ((lane & 3) << 1);
#pragma unroll
        for (int ni = 0; ni < 8; ni++) {
            float v0 = oacc[ni][2*rr] * inv, v1 = oacc[ni][2*rr+1] * inv;
            *reinterpret_cast<__half2*>(&Oh[base + 8 * ni]) = __floats2half2_rn(v0, v1);
        }
    }
}

// ---------------------------------------------------------------------------
// mma.sync fp16 GEMM (1-pass): C[128 x BN] = A[128,K] . B[BN,K]^T, K = NC*64.
// out: fp32 (outf) | split hi/lo (outh+outl) | fp16 (outh)
// ---------------------------------------------------------------------------
template<int BN>
__global__ __launch_bounds__(256)
void mm_gemm(const hf* __restrict__ Ah, int lda,
             const hf* __restrict__ Bh, int ldb,
             float* __restrict__ outf, hf* __restrict__ outh, hf* __restrict__ outl, int ldc,
             const float* __restrict__ bias, const float* __restrict__ res,
             int gelu, int NC)
{
    constexpr int NF  = BN / 16;
    constexpr int ASZ = 128 * 128;
    constexpr int BSZ = BN * 128;
    constexpr int STG = ASZ + BSZ;

    extern __shared__ char smem[];
    const uint32_t sb = (uint32_t)__cvta_generic_to_shared(smem);
    const int tid = threadIdx.x, wid = tid >> 5, lane = tid & 31;
    const int bm = blockIdx.y * 128, bn = blockIdx.x * BN;

    const int wm = (wid & 3) * 32;
    const int wn = (wid >> 2) * (BN / 2);

    auto load_chunk = [&](int c, int s) {
        const uint32_t base = sb + s * STG;
        const int k0 = c * 64;
#pragma unroll
        for (int i = 0; i < 4; i++) {
            int u = tid + i * 256, r = u >> 3, cu = u & 7;
            CP16(base + SWZ(r * 128 + cu * 16), Ah + (size_t)(bm + r) * lda + k0 + cu * 8);
        }
#pragma unroll
        for (int i = 0; i < BN / 32; i++) {
            int u = tid + i * 256, r = u >> 3, cu = u & 7;
            CP16(base + ASZ + SWZ(r * 128 + cu * 16), Bh + (size_t)(bn + r) * ldb + k0 + cu * 8);
        }
    };

    float acc[2][NF][4];
#pragma unroll
    for (int mi = 0; mi < 2; mi++)
#pragma unroll
        for (int ni = 0; ni < NF; ni++)
#pragma unroll
            for (int cc = 0; cc < 4; cc++) acc[mi][ni][cc] = 0.f;

    load_chunk(0, 0);
    asm volatile("cp.async.commit_group;" ::: "memory");

    const int li = lane >> 3, lj = lane & 7;

    for (int c = 0; c < NC; c++) {
        const int s = c & 1;
        if (c + 1 < NC) {
            load_chunk(c + 1, (c + 1) & 1);
            asm volatile("cp.async.commit_group;" ::: "memory");
            asm volatile("cp.async.wait_group 1;" ::: "memory");
        } else {
            asm volatile("cp.async.wait_group 0;" ::: "memory");
        }
        __syncthreads();

        const uint32_t aBase = sb + s * STG;
        const uint32_t bBase = aBase + ASZ;

#pragma unroll
        for (int ks = 0; ks < 4; ks++) {
            const int kb = ks * 16;
            uint32_t ah[2][4];
#pragma unroll
            for (int mi = 0; mi < 2; mi++) {
                int row = wm + mi * 16 + ((li & 1) << 3) + lj;
                int col = kb + ((li >> 1) << 3);
                LDSM4(ah[mi], aBase + SWZ(row * 128 + col * 2));
            }
            uint32_t bh[NF][2];
#pragma unroll
            for (int nt = 0; nt < NF / 2; nt++) {
                int row = wn + nt * 16 + ((li >> 1) << 3) + lj;
                int col = kb + ((li & 1) << 3);
                uint32_t r4[4];
                LDSM4(r4, bBase + SWZ(row * 128 + col * 2));
                bh[2*nt][0] = r4[0]; bh[2*nt][1] = r4[1];
                bh[2*nt+1][0] = r4[2]; bh[2*nt+1][1] = r4[3];
            }
#pragma unroll
            for (int mi = 0; mi < 2; mi++)
#pragma unroll
                for (int ni = 0; ni < NF; ni++) MMA(acc[mi][ni], ah[mi], bh[ni]);
        }
        __syncthreads();
    }

#pragma unroll
    for (int mi = 0; mi < 2; mi++) {
#pragma unroll
        for (int ni = 0; ni < NF; ni++) {
            const int m0 = bm + wm + mi * 16 + (lane >> 2);
            const int n0 = bn + wn + ni * 8 + ((lane & 3) << 1);
#pragma unroll
            for (int rr = 0; rr < 2; rr++) {
                const int m = m0 + rr * 8;
                float v0 = acc[mi][ni][2*rr + 0];
                float v1 = acc[mi][ni][2*rr + 1];
                if (bias) { v0 += bias[n0]; v1 += bias[n0 + 1]; }
                if (gelu) { v0 = gelu_f(v0); v1 = gelu_f(v1); }
                size_t idx = (size_t)m * ldc + n0;
                if (res) { v0 += res[idx]; v1 += res[idx + 1]; }
                if (outf) {
                    outf[idx] = v0; outf[idx + 1] = v1;
                } else if (outl) {
                    __half2 hp = __floats2half2_rn(v0, v1);
                    __half2 lp = __floats2half2_rn(v0 - __low2float(hp), v1 - __high2float(hp));
                    *reinterpret_cast<__half2*>(&outh[idx]) = hp;
                    *reinterpret_cast<__half2*>(&outl[idx]) = lp;
                } else {
                    *reinterpret_cast<__half2*>(&outh[idx]) = __floats2half2_rn(v0, v1);
                }
            }
        }
    }
}

// ---------------------------------------------------------------------------
extern "C" void kernel_launch(void* const* d_in, const int* in_sizes, int n_in,
                              void* d_out, int out_size)
{
    const float* x    = (const float*)d_in[0];
    const int*   mask = (const int*)  d_in[1];
    const float* wq = (const float*)d_in[2],  *bq = (const float*)d_in[3];
    const float* wk = (const float*)d_in[4],  *bk = (const float*)d_in[5];
    const float* wv = (const float*)d_in[6],  *bv = (const float*)d_in[7];
    const float* wo = (const float*)d_in[8],  *bo = (const float*)d_in[9];
    const float* w1 = (const float*)d_in[10], *b1 = (const float*)d_in[11];
    const float* w2 = (const float*)d_in[12], *b2 = (const float*)d_in[13];
    const float* g1 = (const float*)d_in[14], *be1 = (const float*)d_in[15];
    const float* g2 = (const float*)d_in[16], *be2 = (const float*)d_in[17];
    float* out = (float*)d_out;

    hf *xnh,*qh,*ql,*kh,*vh,*oh,*h1h;
    hf *wqc,*wkc,*wvc,*woc,*w1c,*w2c;
    cudaGetSymbolAddress((void**)&xnh, g_xnh);
    cudaGetSymbolAddress((void**)&qh, g_qh);   cudaGetSymbolAddress((void**)&ql, g_ql);
    cudaGetSymbolAddress((void**)&kh, g_kh);   cudaGetSymbolAddress((void**)&vh, g_vh);
    cudaGetSymbolAddress((void**)&oh, g_oh);   cudaGetSymbolAddress((void**)&h1h, g_h1h);
    cudaGetSymbolAddress((void**)&wqc, g_wq);  cudaGetSymbolAddress((void**)&wkc, g_wk);
    cudaGetSymbolAddress((void**)&wvc, g_wv);  cudaGetSymbolAddress((void**)&woc, g_wo);
    cudaGetSymbolAddress((void**)&w1c, g_w1);  cudaGetSymbolAddress((void**)&w2c, g_w2);

    const int SMONE = 2 * (16384 + 16384);       // 65536
    const int SMFL  = 32768 + 2 * 32768;         // 98304
    cudaFuncSetAttribute((const void*)mm_gemm<128>, cudaFuncAttributeMaxDynamicSharedMemorySize, SMONE);
    cudaFuncSetAttribute((const void*)flash_kernel, cudaFuncAttributeMaxDynamicSharedMemorySize, SMFL);

    // weight conversions (fp16)
    conv_kernel<<<1024, 256>>>(wq, wqc, CD * CD / 4);
    conv_kernel<<<1024, 256>>>(wk, wkc, CD * CD / 4);
    conv_kernel<<<1024, 256>>>(wv, wvc, CD * CD / 4);
    conv_kernel<<<1024, 256>>>(wo, woc, CD * CD / 4);
    conv_kernel<<<4096, 256>>>(w1, w1c, CDFF * CD / 4);
    conv_kernel<<<4096, 256>>>(w2, w2c, CD * CDFF / 4);

    // LN1 -> xn (fp16)
    ln_kernel<<<NTOK, 256>>>(x, g1, be1, xnh);

    // QKV projections (1-pass): Q accumulator split at epilogue, K/V fp16
    dim3 gD(CD / 128, NTOK / 128);
    mm_gemm<128><<<gD, 256, SMONE>>>(xnh, CD, wqc, CD,
        nullptr, qh, ql, CD, bq, nullptr, 0, 16);
    mm_gemm<128><<<gD, 256, SMONE>>>(xnh, CD, wkc, CD,
        nullptr, kh, nullptr, CD, bk, nullptr, 0, 16);
    mm_gemm<128><<<gD, 256, SMONE>>>(xnh, CD, wvc, CD,
        nullptr, vh, nullptr, CD, bv, nullptr, 0, 16);

    // fused attention -> O (fp16)
    dim3 gA(CS / 128, CB * CH);
    flash_kernel<<<gA, 256, SMFL>>>(qh, ql, kh, vh, mask, oh);

    // x1 = O wo^T + bo + x -> out (fp32)
    mm_gemm<128><<<gD, 256, SMONE>>>(oh, CD, woc, CD,
        out, nullptr, nullptr, CD, bo, x, 0, 16);

    // LN2 -> xn (fp16)
    ln_kernel<<<NTOK, 256>>>(out, g2, be2, xnh);

    // h1 = gelu(xn w1^T + b1) (fp16)
    dim3 gF(CDFF / 128, NTOK / 128);
    mm_gemm<128><<<gF, 256, SMONE>>>(xnh, CD, w1c, CD,
        nullptr, h1h, nullptr, CDFF, b1, nullptr, 1, 16);

    // out = x1 + h1 w2^T + b2
    mm_gemm<128><<<gD, 256, SMONE>>>(h1h, CDFF, w2c, CDFF,
        out, nullptr, nullptr, CD, b2, out, 0, 64);
}

// round 9
// speedup vs baseline: 7.5718x; 1.1122x over previous
#include <cuda_runtime.h>
#include <cuda_fp16.h>
#include <math.h>
#include <stdint.h>

#define CB 8
#define CS 1024
#define CD 1024
#define CH 16
#define CDK 64
#define CDFF 4096
#define NTOK (CB*CS)
#define CQKV 3072
typedef __half hf;

#define SWZ(o) ((o) ^ (((o) >> 3) & 0x70))
#define CP16(dst, src) asm volatile("cp.async.cg.shared.global [%0], [%1], 16;" :: "r"(dst), "l"(src) : "memory")

#define LDSM4(r, a) \
    asm volatile("ldmatrix.sync.aligned.m8n8.x4.shared.b16 {%0,%1,%2,%3}, [%4];" \
        : "=r"((r)[0]), "=r"((r)[1]), "=r"((r)[2]), "=r"((r)[3]) : "r"(a))
#define LDSM4T(r, a) \
    asm volatile("ldmatrix.sync.aligned.m8n8.x4.trans.shared.b16 {%0,%1,%2,%3}, [%4];" \
        : "=r"((r)[0]), "=r"((r)[1]), "=r"((r)[2]), "=r"((r)[3]) : "r"(a))

#define MMA(c, a, b) \
    asm volatile("mma.sync.aligned.m16n8k16.row.col.f32.f16.f16.f32 " \
        "{%0,%1,%2,%3},{%4,%5,%6,%7},{%8,%9},{%0,%1,%2,%3};" \
        : "+f"((c)[0]), "+f"((c)[1]), "+f"((c)[2]), "+f"((c)[3]) \
        : "r"((a)[0]), "r"((a)[1]), "r"((a)[2]), "r"((a)[3]), "r"((b)[0]), "r"((b)[1]))

__device__ __forceinline__ float gelu_f(float x) {
    float x3 = x * x * x;
    return 0.5f * x * (1.0f + tanhf(0.7978845608028654f * (x + 0.044715f * x3)));
}

// ------------------------- scratch -------------------------
__device__ hf g_xnh[NTOK*CD];
__device__ hf g_qkv[(size_t)NTOK*CQKV];          // [B,S, (Q|K|V) x H*DK]
__device__ hf g_oh[NTOK*CD];
__device__ hf g_h1h[(size_t)NTOK*CDFF];
__device__ hf g_wqkv[(size_t)CQKV*CD];           // rows: wq*0.125 | wk | wv
__device__ float g_bqkv[CQKV];
__device__ hf g_wo[CD*CD];
__device__ hf g_w1[(size_t)CDFF*CD], g_w2[(size_t)CD*CDFF];

__global__ __launch_bounds__(256)
void conv_kernel(const float* __restrict__ w, hf* __restrict__ h, int n4, float scale) {
    int i = blockIdx.x * 256 + threadIdx.x;
    if (i < n4) {
        float4 v = reinterpret_cast<const float4*>(w)[i];
        reinterpret_cast<__half2*>(h)[2*i]   = __floats2half2_rn(v.x * scale, v.y * scale);
        reinterpret_cast<__half2*>(h)[2*i+1] = __floats2half2_rn(v.z * scale, v.w * scale);
    }
}

__global__ __launch_bounds__(256)
void bias_pack_kernel(const float* __restrict__ bq, const float* __restrict__ bk,
                      const float* __restrict__ bv, float* __restrict__ o) {
    int i = blockIdx.x * 256 + threadIdx.x;
    if (i < CD)            o[i] = bq[i] * 0.125f;
    else if (i < 2 * CD)   o[i] = bk[i - CD];
    else if (i < 3 * CD)   o[i] = bv[i - 2 * CD];
}

// ------------------------- LayerNorm (ddof=1, eps on std) -> fp16 -------------------------
__global__ __launch_bounds__(256)
void ln_kernel(const float* __restrict__ x, const float* __restrict__ gamma,
               const float* __restrict__ beta, hf* __restrict__ oh) {
    const int row = blockIdx.x;
    const float* xr = x + (size_t)row * CD;
    const int t = threadIdx.x;
    float v[4];
#pragma unroll
    for (int i = 0; i < 4; i++) v[i] = xr[t + 256 * i];
    __shared__ float red[8];
    __shared__ float s_mean, s_rstd;
    float s = v[0] + v[1] + v[2] + v[3];
#pragma unroll
    for (int o = 16; o > 0; o >>= 1) s += __shfl_xor_sync(~0u, s, o);
    if ((t & 31) == 0) red[t >> 5] = s;
    __syncthreads();
    if (t < 8) {
        float r = red[t];
#pragma unroll
        for (int o = 4; o > 0; o >>= 1) r += __shfl_xor_sync(0xffu, r, o);
        if (t == 0) s_mean = r * (1.0f / CD);
    }
    __syncthreads();
    const float mean = s_mean;
    float q = 0.f;
#pragma unroll
    for (int i = 0; i < 4; i++) { float d = v[i] - mean; q += d * d; }
#pragma unroll
    for (int o = 16; o > 0; o >>= 1) q += __shfl_xor_sync(~0u, q, o);
    if ((t & 31) == 0) red[t >> 5] = q;
    __syncthreads();
    if (t < 8) {
        float r = red[t];
#pragma unroll
        for (int o = 4; o > 0; o >>= 1) r += __shfl_xor_sync(0xffu, r, o);
        if (t == 0) s_rstd = 1.0f / (sqrtf(r * (1.0f / (CD - 1))) + 1e-5f);
    }
    __syncthreads();
    const float rstd = s_rstd;
#pragma unroll
    for (int i = 0; i < 4; i++) {
        int c = t + 256 * i;
        oh[(size_t)row * CD + c] = __float2half_rn(gamma[c] * (v[i] - mean) * rstd + beta[c]);
    }
}

// ---------------------------------------------------------------------------
// Flash attention: O = softmax(mask(Q K^T)) V with Q pre-scaled by 0.125.
// All fp16 operands, 1-pass MMA both GEMMs. QKV packed [B,S,3072].
// SMEM: Q 16K + 2 stages x (K 16K + V 16K) = 80 KB -> 2 CTA/SM.
// ---------------------------------------------------------------------------
__global__ __launch_bounds__(256)
void flash_kernel(const hf* __restrict__ QKV, const int* __restrict__ mask,
                  hf* __restrict__ Oh)
{
    extern __shared__ char smem[];
    const uint32_t sb = (uint32_t)__cvta_generic_to_shared(smem);
    const int tid = threadIdx.x, wid = tid >> 5, lane = tid & 31;
    const int qt = blockIdx.x, z = blockIdx.y;
    const int b = z >> 4, h = z & 15;
    const int qbase = qt * 128;
    const size_t headOff = (size_t)h * 64;

    auto gaddr = [&](int part, int srow, int cu) {
        return QKV + ((size_t)(b * CS + srow) * CQKV + part * CD + headOff + (cu << 3));
    };

#pragma unroll
    for (int i = 0; i < 4; i++) {
        int u = tid + i * 256, r = u >> 3, cu = u & 7;
        CP16(sb + SWZ(r * 128 + cu * 16), gaddr(0, qbase + r, cu));
    }

    auto loadKV = [&](int it, int s) {
        const uint32_t base = sb + 16384 + s * 32768;
        const int kb = it * 128;
#pragma unroll
        for (int i = 0; i < 4; i++) {
            int u = tid + i * 256, r = u >> 3, cu = u & 7;
            uint32_t sw = SWZ(r * 128 + cu * 16);
            CP16(base + sw,         gaddr(1, kb + r, cu));
            CP16(base + 16384 + sw, gaddr(2, kb + r, cu));
        }
    };

    loadKV(0, 0);
    asm volatile("cp.async.commit_group;" ::: "memory");
    loadKV(1, 1);
    asm volatile("cp.async.commit_group;" ::: "memory");

    float oacc[8][4];
#pragma unroll
    for (int i = 0; i < 8; i++)
#pragma unroll
        for (int j = 0; j < 4; j++) oacc[i][j] = 0.f;
    float m_old[2] = {-INFINITY, -INFINITY};
    float l_sum[2] = {0.f, 0.f};

    const int li = lane >> 3, lj = lane & 7;
    const int rbase = wid * 16 + (lane >> 2);

    for (int it = 0; it < 8; it++) {
        const int s = it & 1;
        if (it < 7) asm volatile("cp.async.wait_group 1;" ::: "memory");
        else        asm volatile("cp.async.wait_group 0;" ::: "memory");
        __syncthreads();

        const uint32_t kst = sb + 16384 + s * 32768;
        const uint32_t vst = kst + 16384;

        // ---- S = Q K^T (1-pass, Q pre-scaled by 0.125) ----
        float sacc[16][4];
#pragma unroll
        for (int i = 0; i < 16; i++)
#pragma unroll
            for (int j = 0; j < 4; j++) sacc[i][j] = 0.f;

#pragma unroll
        for (int kk = 0; kk < 4; kk++) {
            uint32_t ah[4];
            uint32_t aoff = SWZ((wid * 16 + ((li & 1) << 3) + lj) * 128 + (kk * 16 + ((li >> 1) << 3)) * 2);
            LDSM4(ah, sb + aoff);
            uint32_t bh[8][4];
#pragma unroll
            for (int nt = 0; nt < 8; nt++) {
                uint32_t off = SWZ((nt * 16 + ((li >> 1) << 3) + lj) * 128 + (kk * 16 + ((li & 1) << 3)) * 2);
                LDSM4(bh[nt], kst + off);
            }
#pragma unroll
            for (int nt = 0; nt < 8; nt++) { MMA(sacc[2*nt], ah, bh[nt]); MMA(sacc[2*nt+1], ah, bh[nt]+2); }
        }

        // ---- mask + online softmax ----
#pragma unroll
        for (int rr = 0; rr < 2; rr++) {
            const int grow = qbase + rbase + rr * 8;
            const int2* mrow = (const int2*)(mask + ((size_t)(b * CS + grow)) * CS + it * 128 + ((lane & 3) << 1));
            float mx = -INFINITY;
#pragma unroll
            for (int ni = 0; ni < 16; ni++) {
                int2 mv = mrow[ni * 4];
                float v0 = mv.x ? sacc[ni][2*rr]   : -1e9f;
                float v1 = mv.y ? sacc[ni][2*rr+1] : -1e9f;
                sacc[ni][2*rr] = v0; sacc[ni][2*rr+1] = v1;
                mx = fmaxf(mx, fmaxf(v0, v1));
            }
            mx = fmaxf(mx, __shfl_xor_sync(~0u, mx, 1));
            mx = fmaxf(mx, __shfl_xor_sync(~0u, mx, 2));
            const float mnew = fmaxf(m_old[rr], mx);
            const float scl = __expf(m_old[rr] - mnew);
            float rsum = 0.f;
#pragma unroll
            for (int ni = 0; ni < 16; ni++) {
                float p0 = __expf(sacc[ni][2*rr]   - mnew);
                float p1 = __expf(sacc[ni][2*rr+1] - mnew);
                sacc[ni][2*rr] = p0; sacc[ni][2*rr+1] = p1;
                rsum += p0 + p1;
            }
            rsum += __shfl_xor_sync(~0u, rsum, 1);
            rsum += __shfl_xor_sync(~0u, rsum, 2);
            l_sum[rr] = l_sum[rr] * scl + rsum;
            m_old[rr] = mnew;
#pragma unroll
            for (int ni = 0; ni < 8; ni++) { oacc[ni][2*rr] *= scl; oacc[ni][2*rr+1] *= scl; }
        }

        // ---- O += P V (1-pass; P packed fp16, V via ldmatrix.trans) ----
#pragma unroll
        for (int kk = 0; kk < 8; kk++) {
            uint32_t ah2[4];
            const int f0 = 2 * kk, f1 = 2 * kk + 1;
            {
                __half2 h0 = __floats2half2_rn(sacc[f0][0], sacc[f0][1]);
                __half2 h1 = __floats2half2_rn(sacc[f0][2], sacc[f0][3]);
                __half2 h2 = __floats2half2_rn(sacc[f1][0], sacc[f1][1]);
                __half2 h3 = __floats2half2_rn(sacc[f1][2], sacc[f1][3]);
                ah2[0] = *reinterpret_cast<uint32_t*>(&h0);
                ah2[1] = *reinterpret_cast<uint32_t*>(&h1);
                ah2[2] = *reinterpret_cast<uint32_t*>(&h2);
                ah2[3] = *reinterpret_cast<uint32_t*>(&h3);
            }
            uint32_t vf[4][4];
#pragma unroll
            for (int nb = 0; nb < 4; nb++) {
                uint32_t off = SWZ((kk * 16 + ((li & 1) << 3) + lj) * 128 + (nb * 16 + ((li >> 1) << 3)) * 2);
                LDSM4T(vf[nb], vst + off);
            }
#pragma unroll
            for (int nb = 0; nb < 4; nb++) { MMA(oacc[2*nb], ah2, vf[nb]); MMA(oacc[2*nb+1], ah2, vf[nb]+2); }
        }

        __syncthreads();
        if (it + 2 < 8) {
            loadKV(it + 2, s);
            asm volatile("cp.async.commit_group;" ::: "memory");
        }
    }

#pragma unroll
    for (int rr = 0; rr < 2; rr++) {
        const int grow = qbase + rbase + rr * 8;
        const float inv = 1.f / l_sum[rr];
        const size_t base = (size_t)(b * CS + grow) * CD + headOff + ((lane & 3) << 1);
#pragma unroll
        for (int ni = 0; ni < 8; ni++) {
            float v0 = oacc[ni][2*rr] * inv, v1 = oacc[ni][2*rr+1] * inv;
            *reinterpret_cast<__half2*>(&Oh[base + 8 * ni]) = __floats2half2_rn(v0, v1);
        }
    }
}

// ---------------------------------------------------------------------------
// mma.sync fp16 GEMM (1-pass, 3-stage pipeline): C[128 x 128] = A . B^T, K=NC*64.
// out: fp32 (outf) | fp16 (outh)
// ---------------------------------------------------------------------------
__global__ __launch_bounds__(256)
void mm_gemm(const hf* __restrict__ Ah, int lda,
             const hf* __restrict__ Bh, int ldb,
             float* __restrict__ outf, hf* __restrict__ outh, int ldc,
             const float* __restrict__ bias, const float* __restrict__ res,
             int gelu, int NC)
{
    constexpr int BN  = 128;
    constexpr int NF  = BN / 16;
    constexpr int ASZ = 128 * 128;
    constexpr int STG = 2 * ASZ;            // A 16K + B 16K

    extern __shared__ char smem[];
    const uint32_t sb = (uint32_t)__cvta_generic_to_shared(smem);
    const int tid = threadIdx.x, wid = tid >> 5, lane = tid & 31;
    const int bm = blockIdx.y * 128, bn = blockIdx.x * BN;

    const int wm = (wid & 3) * 32;
    const int wn = (wid >> 2) * (BN / 2);

    auto load_chunk = [&](int c, int s) {
        const uint32_t base = sb + s * STG;
        const int k0 = c * 64;
#pragma unroll
        for (int i = 0; i < 4; i++) {
            int u = tid + i * 256, r = u >> 3, cu = u & 7;
            CP16(base + SWZ(r * 128 + cu * 16), Ah + (size_t)(bm + r) * lda + k0 + cu * 8);
        }
#pragma unroll
        for (int i = 0; i < 4; i++) {
            int u = tid + i * 256, r = u >> 3, cu = u & 7;
            CP16(base + ASZ + SWZ(r * 128 + cu * 16), Bh + (size_t)(bn + r) * ldb + k0 + cu * 8);
        }
    };

    float acc[2][NF][4];
#pragma unroll
    for (int mi = 0; mi < 2; mi++)
#pragma unroll
        for (int ni = 0; ni < NF; ni++)
#pragma unroll
            for (int cc = 0; cc < 4; cc++) acc[mi][ni][cc] = 0.f;

    load_chunk(0, 0);
    asm volatile("cp.async.commit_group;" ::: "memory");
    load_chunk(1, 1);
    asm volatile("cp.async.commit_group;" ::: "memory");

    const int li = lane >> 3, lj = lane & 7;

    for (int c = 0; c < NC; c++) {
        if (c + 2 < NC) {
            load_chunk(c + 2, (c + 2) % 3);
            asm volatile("cp.async.commit_group;" ::: "memory");
            asm volatile("cp.async.wait_group 2;" ::: "memory");
        } else if (c + 1 < NC) {
            asm volatile("cp.async.wait_group 1;" ::: "memory");
        } else {
            asm volatile("cp.async.wait_group 0;" ::: "memory");
        }
        __syncthreads();

        const uint32_t aBase = sb + (c % 3) * STG;
        const uint32_t bBase = aBase + ASZ;

#pragma unroll
        for (int ks = 0; ks < 4; ks++) {
            const int kb = ks * 16;
            uint32_t ah[2][4];
#pragma unroll
            for (int mi = 0; mi < 2; mi++) {
                int row = wm + mi * 16 + ((li & 1) << 3) + lj;
                int col = kb + ((li >> 1) << 3);
                LDSM4(ah[mi], aBase + SWZ(row * 128 + col * 2));
            }
            uint32_t bh[NF][2];
#pragma unroll
            for (int nt = 0; nt < NF / 2; nt++) {
                int row = wn + nt * 16 + ((li >> 1) << 3) + lj;
                int col = kb + ((li & 1) << 3);
                uint32_t r4[4];
                LDSM4(r4, bBase + SWZ(row * 128 + col * 2));
                bh[2*nt][0] = r4[0]; bh[2*nt][1] = r4[1];
                bh[2*nt+1][0] = r4[2]; bh[2*nt+1][1] = r4[3];
            }
#pragma unroll
            for (int mi = 0; mi < 2; mi++)
#pragma unroll
                for (int ni = 0; ni < NF; ni++) MMA(acc[mi][ni], ah[mi], bh[ni]);
        }
        __syncthreads();
    }

#pragma unroll
    for (int mi = 0; mi < 2; mi++) {
#pragma unroll
        for (int ni = 0; ni < NF; ni++) {
            const int m0 = bm + wm + mi * 16 + (lane >> 2);
            const int n0 = bn + wn + ni * 8 + ((lane & 3) << 1);
#pragma unroll
            for (int rr = 0; rr < 2; rr++) {
                const int m = m0 + rr * 8;
                float v0 = acc[mi][ni][2*rr + 0];
                float v1 = acc[mi][ni][2*rr + 1];
                if (bias) { v0 += bias[n0]; v1 += bias[n0 + 1]; }
                if (gelu) { v0 = gelu_f(v0); v1 = gelu_f(v1); }
                size_t idx = (size_t)m * ldc + n0;
                if (res) { v0 += res[idx]; v1 += res[idx + 1]; }
                if (outf) {
                    outf[idx] = v0; outf[idx + 1] = v1;
                } else {
                    *reinterpret_cast<__half2*>(&outh[idx]) = __floats2half2_rn(v0, v1);
                }
            }
        }
    }
}

// ---------------------------------------------------------------------------
extern "C" void kernel_launch(void* const* d_in, const int* in_sizes, int n_in,
                              void* d_out, int out_size)
{
    const float* x    = (const float*)d_in[0];
    const int*   mask = (const int*)  d_in[1];
    const float* wq = (const float*)d_in[2],  *bq = (const float*)d_in[3];
    const float* wk = (const float*)d_in[4],  *bk = (const float*)d_in[5];
    const float* wv = (const float*)d_in[6],  *bv = (const float*)d_in[7];
    const float* wo = (const float*)d_in[8],  *bo = (const float*)d_in[9];
    const float* w1 = (const float*)d_in[10], *b1 = (const float*)d_in[11];
    const float* w2 = (const float*)d_in[12], *b2 = (const float*)d_in[13];
    const float* g1 = (const float*)d_in[14], *be1 = (const float*)d_in[15];
    const float* g2 = (const float*)d_in[16], *be2 = (const float*)d_in[17];
    float* out = (float*)d_out;

    hf *xnh,*qkv,*oh,*h1h,*wqkvc,*woc,*w1c,*w2c;
    float *bqkv;
    cudaGetSymbolAddress((void**)&xnh, g_xnh);
    cudaGetSymbolAddress((void**)&qkv, g_qkv);
    cudaGetSymbolAddress((void**)&oh, g_oh);
    cudaGetSymbolAddress((void**)&h1h, g_h1h);
    cudaGetSymbolAddress((void**)&wqkvc, g_wqkv);
    cudaGetSymbolAddress((void**)&bqkv, g_bqkv);
    cudaGetSymbolAddress((void**)&woc, g_wo);
    cudaGetSymbolAddress((void**)&w1c, g_w1);
    cudaGetSymbolAddress((void**)&w2c, g_w2);

    const int SMGM = 3 * 32768;              // 98304, 3-stage
    const int SMFL = 16384 + 2 * 32768;      // 81920
    cudaFuncSetAttribute((const void*)mm_gemm, cudaFuncAttributeMaxDynamicSharedMemorySize, SMGM);
    cudaFuncSetAttribute((const void*)flash_kernel, cudaFuncAttributeMaxDynamicSharedMemorySize, SMFL);

    // pack weights: wq*0.125 | wk | wv into g_wqkv; bias packed likewise
    conv_kernel<<<1024, 256>>>(wq, wqkvc,               CD * CD / 4, 0.125f);
    conv_kernel<<<1024, 256>>>(wk, wqkvc + CD * CD,     CD * CD / 4, 1.0f);
    conv_kernel<<<1024, 256>>>(wv, wqkvc + 2 * CD * CD, CD * CD / 4, 1.0f);
    bias_pack_kernel<<<12, 256>>>(bq, bk, bv, bqkv);
    conv_kernel<<<1024, 256>>>(wo, woc, CD * CD / 4, 1.0f);
    conv_kernel<<<4096, 256>>>(w1, w1c, CDFF * CD / 4, 1.0f);
    conv_kernel<<<4096, 256>>>(w2, w2c, CD * CDFF / 4, 1.0f);

    // LN1 -> xn (fp16)
    ln_kernel<<<NTOK, 256>>>(x, g1, be1, xnh);

    // fused QKV projection -> [B,S,3072] (Q pre-scaled by 0.125)
    dim3 gQKV(CQKV / 128, NTOK / 128);
    mm_gemm<<<gQKV, 256, SMGM>>>(xnh, CD, wqkvc, CD,
        nullptr, qkv, CQKV, bqkv, nullptr, 0, 16);

    // fused attention -> O (fp16)
    dim3 gA(CS / 128, CB * CH);
    flash_kernel<<<gA, 256, SMFL>>>(qkv, mask, oh);

    // x1 = O wo^T + bo + x -> out (fp32)
    dim3 gD(CD / 128, NTOK / 128);
    mm_gemm<<<gD, 256, SMGM>>>(oh, CD, woc, CD,
        out, nullptr, CD, bo, x, 0, 16);

    // LN2 -> xn (fp16)
    ln_kernel<<<NTOK, 256>>>(out, g2, be2, xnh);

    // h1 = gelu(xn w1^T + b1) (fp16)
    dim3 gF(CDFF / 128, NTOK / 128);
    mm_gemm<<<gF, 256, SMGM>>>(xnh, CD, w1c, CD,
        nullptr, h1h, CDFF, b1, nullptr, 1, 16);

    // out = x1 + h1 w2^T + b2
    mm_gemm<<<gD, 256, SMGM>>>(h1h, CDFF, w2c, CDFF,
        out, nullptr, CD, b2, out, 0, 64);
}

// round 10
// speedup vs baseline: 7.5943x; 1.0030x over previous
#include <cuda_runtime.h>
#include <cuda_fp16.h>
#include <math.h>
#include <stdint.h>

#define CB 8
#define CS 1024
#define CD 1024
#define CH 16
#define CDK 64
#define CDFF 4096
#define NTOK (CB*CS)
#define CQKV 3072
typedef __half hf;

#define SWZ(o) ((o) ^ (((o) >> 3) & 0x70))
#define CP16(dst, src) asm volatile("cp.async.cg.shared.global [%0], [%1], 16;" :: "r"(dst), "l"(src) : "memory")

#define LDSM4(r, a) \
    asm volatile("ldmatrix.sync.aligned.m8n8.x4.shared.b16 {%0,%1,%2,%3}, [%4];" \
        : "=r"((r)[0]), "=r"((r)[1]), "=r"((r)[2]), "=r"((r)[3]) : "r"(a))
#define LDSM4T(r, a) \
    asm volatile("ldmatrix.sync.aligned.m8n8.x4.trans.shared.b16 {%0,%1,%2,%3}, [%4];" \
        : "=r"((r)[0]), "=r"((r)[1]), "=r"((r)[2]), "=r"((r)[3]) : "r"(a))

#define MMA(c, a, b) \
    asm volatile("mma.sync.aligned.m16n8k16.row.col.f32.f16.f16.f32 " \
        "{%0,%1,%2,%3},{%4,%5,%6,%7},{%8,%9},{%0,%1,%2,%3};" \
        : "+f"((c)[0]), "+f"((c)[1]), "+f"((c)[2]), "+f"((c)[3]) \
        : "r"((a)[0]), "r"((a)[1]), "r"((a)[2]), "r"((a)[3]), "r"((b)[0]), "r"((b)[1]))

__device__ __forceinline__ float gelu_f(float x) {
    float x3 = x * x * x;
    return 0.5f * x * (1.0f + tanhf(0.7978845608028654f * (x + 0.044715f * x3)));
}

// ------------------------- scratch -------------------------
__device__ hf g_xnh[NTOK*CD];
__device__ hf g_qkv[(size_t)NTOK*CQKV];          // [B,S, (Q|K|V) x H*DK]
__device__ hf g_oh[NTOK*CD];
__device__ hf g_h1h[(size_t)NTOK*CDFF];
__device__ hf g_wqkv[(size_t)CQKV*CD];           // rows: wq*0.125 | wk | wv
__device__ float g_bqkv[CQKV];
__device__ hf g_wo[CD*CD];
__device__ hf g_w1[(size_t)CDFF*CD], g_w2[(size_t)CD*CDFF];

__global__ __launch_bounds__(256)
void conv_kernel(const float* __restrict__ w, hf* __restrict__ h, int n4, float scale) {
    int i = blockIdx.x * 256 + threadIdx.x;
    if (i < n4) {
        float4 v = reinterpret_cast<const float4*>(w)[i];
        reinterpret_cast<__half2*>(h)[2*i]   = __floats2half2_rn(v.x * scale, v.y * scale);
        reinterpret_cast<__half2*>(h)[2*i+1] = __floats2half2_rn(v.z * scale, v.w * scale);
    }
}

__global__ __launch_bounds__(256)
void bias_pack_kernel(const float* __restrict__ bq, const float* __restrict__ bk,
                      const float* __restrict__ bv, float* __restrict__ o) {
    int i = blockIdx.x * 256 + threadIdx.x;
    if (i < CD)            o[i] = bq[i] * 0.125f;
    else if (i < 2 * CD)   o[i] = bk[i - CD];
    else if (i < 3 * CD)   o[i] = bv[i - 2 * CD];
}

// ------------------------- LayerNorm (ddof=1, eps on std) -> fp16 -------------------------
__global__ __launch_bounds__(256)
void ln_kernel(const float* __restrict__ x, const float* __restrict__ gamma,
               const float* __restrict__ beta, hf* __restrict__ oh) {
    const int row = blockIdx.x;
    const float* xr = x + (size_t)row * CD;
    const int t = threadIdx.x;
    float v[4];
#pragma unroll
    for (int i = 0; i < 4; i++) v[i] = xr[t + 256 * i];
    __shared__ float red[8];
    __shared__ float s_mean, s_rstd;
    float s = v[0] + v[1] + v[2] + v[3];
#pragma unroll
    for (int o = 16; o > 0; o >>= 1) s += __shfl_xor_sync(~0u, s, o);
    if ((t & 31) == 0) red[t >> 5] = s;
    __syncthreads();
    if (t < 8) {
        float r = red[t];
#pragma unroll
        for (int o = 4; o > 0; o >>= 1) r += __shfl_xor_sync(0xffu, r, o);
        if (t == 0) s_mean = r * (1.0f / CD);
    }
    __syncthreads();
    const float mean = s_mean;
    float q = 0.f;
#pragma unroll
    for (int i = 0; i < 4; i++) { float d = v[i] - mean; q += d * d; }
#pragma unroll
    for (int o = 16; o > 0; o >>= 1) q += __shfl_xor_sync(~0u, q, o);
    if ((t & 31) == 0) red[t >> 5] = q;
    __syncthreads();
    if (t < 8) {
        float r = red[t];
#pragma unroll
        for (int o = 4; o > 0; o >>= 1) r += __shfl_xor_sync(0xffu, r, o);
        if (t == 0) s_rstd = 1.0f / (sqrtf(r * (1.0f / (CD - 1))) + 1e-5f);
    }
    __syncthreads();
    const float rstd = s_rstd;
#pragma unroll
    for (int i = 0; i < 4; i++) {
        int c = t + 256 * i;
        oh[(size_t)row * CD + c] = __float2half_rn(gamma[c] * (v[i] - mean) * rstd + beta[c]);
    }
}

// ---------------------------------------------------------------------------
// Flash attention: O = softmax(mask(Q K^T)) V with Q pre-scaled by 0.125.
// All fp16 operands, 1-pass MMA both GEMMs. QKV packed [B,S,3072].
// ---------------------------------------------------------------------------
__global__ __launch_bounds__(256)
void flash_kernel(const hf* __restrict__ QKV, const int* __restrict__ mask,
                  hf* __restrict__ Oh)
{
    extern __shared__ char smem[];
    const uint32_t sb = (uint32_t)__cvta_generic_to_shared(smem);
    const int tid = threadIdx.x, wid = tid >> 5, lane = tid & 31;
    const int qt = blockIdx.x, z = blockIdx.y;
    const int b = z >> 4, h = z & 15;
    const int qbase = qt * 128;
    const size_t headOff = (size_t)h * 64;

    auto gaddr = [&](int part, int srow, int cu) {
        return QKV + ((size_t)(b * CS + srow) * CQKV + part * CD + headOff + (cu << 3));
    };

#pragma unroll
    for (int i = 0; i < 4; i++) {
        int u = tid + i * 256, r = u >> 3, cu = u & 7;
        CP16(sb + SWZ(r * 128 + cu * 16), gaddr(0, qbase + r, cu));
    }

    auto loadKV = [&](int it, int s) {
        const uint32_t base = sb + 16384 + s * 32768;
        const int kb = it * 128;
#pragma unroll
        for (int i = 0; i < 4; i++) {
            int u = tid + i * 256, r = u >> 3, cu = u & 7;
            uint32_t sw = SWZ(r * 128 + cu * 16);
            CP16(base + sw,         gaddr(1, kb + r, cu));
            CP16(base + 16384 + sw, gaddr(2, kb + r, cu));
        }
    };

    loadKV(0, 0);
    asm volatile("cp.async.commit_group;" ::: "memory");
    loadKV(1, 1);
    asm volatile("cp.async.commit_group;" ::: "memory");

    float oacc[8][4];
#pragma unroll
    for (int i = 0; i < 8; i++)
#pragma unroll
        for (int j = 0; j < 4; j++) oacc[i][j] = 0.f;
    float m_old[2] = {-INFINITY, -INFINITY};
    float l_sum[2] = {0.f, 0.f};

    const int li = lane >> 3, lj = lane & 7;
    const int rbase = wid * 16 + (lane >> 2);

    for (int it = 0; it < 8; it++) {
        const int s = it & 1;
        if (it < 7) asm volatile("cp.async.wait_group 1;" ::: "memory");
        else        asm volatile("cp.async.wait_group 0;" ::: "memory");
        __syncthreads();

        const uint32_t kst = sb + 16384 + s * 32768;
        const uint32_t vst = kst + 16384;

        float sacc[16][4];
#pragma unroll
        for (int i = 0; i < 16; i++)
#pragma unroll
            for (int j = 0; j < 4; j++) sacc[i][j] = 0.f;

#pragma unroll
        for (int kk = 0; kk < 4; kk++) {
            uint32_t ah[4];
            uint32_t aoff = SWZ((wid * 16 + ((li & 1) << 3) + lj) * 128 + (kk * 16 + ((li >> 1) << 3)) * 2);
            LDSM4(ah, sb + aoff);
            uint32_t bh[8][4];
#pragma unroll
            for (int nt = 0; nt < 8; nt++) {
                uint32_t off = SWZ((nt * 16 + ((li >> 1) << 3) + lj) * 128 + (kk * 16 + ((li & 1) << 3)) * 2);
                LDSM4(bh[nt], kst + off);
            }
#pragma unroll
            for (int nt = 0; nt < 8; nt++) { MMA(sacc[2*nt], ah, bh[nt]); MMA(sacc[2*nt+1], ah, bh[nt]+2); }
        }

#pragma unroll
        for (int rr = 0; rr < 2; rr++) {
            const int grow = qbase + rbase + rr * 8;
            const int2* mrow = (const int2*)(mask + ((size_t)(b * CS + grow)) * CS + it * 128 + ((lane & 3) << 1));
            float mx = -INFINITY;
#pragma unroll
            for (int ni = 0; ni < 16; ni++) {
                int2 mv = mrow[ni * 4];
                float v0 = mv.x ? sacc[ni][2*rr]   : -1e9f;
                float v1 = mv.y ? sacc[ni][2*rr+1] : -1e9f;
                sacc[ni][2*rr] = v0; sacc[ni][2*rr+1] = v1;
                mx = fmaxf(mx, fmaxf(v0, v1));
            }
            mx = fmaxf(mx, __shfl_xor_sync(~0u, mx, 1));
            mx = fmaxf(mx, __shfl_xor_sync(~0u, mx, 2));
            const float mnew = fmaxf(m_old[rr], mx);
            const float scl = __expf(m_old[rr] - mnew);
            float rsum = 0.f;
#pragma unroll
            for (int ni = 0; ni < 16; ni++) {
                float p0 = __expf(sacc[ni][2*rr]   - mnew);
                float p1 = __expf(sacc[ni][2*rr+1] - mnew);
                sacc[ni][2*rr] = p0; sacc[ni][2*rr+1] = p1;
                rsum += p0 + p1;
            }
            rsum += __shfl_xor_sync(~0u, rsum, 1);
            rsum += __shfl_xor_sync(~0u, rsum, 2);
            l_sum[rr] = l_sum[rr] * scl + rsum;
            m_old[rr] = mnew;
#pragma unroll
            for (int ni = 0; ni < 8; ni++) { oacc[ni][2*rr] *= scl; oacc[ni][2*rr+1] *= scl; }
        }

#pragma unroll
        for (int kk = 0; kk < 8; kk++) {
            uint32_t ah2[4];
            const int f0 = 2 * kk, f1 = 2 * kk + 1;
            {
                __half2 h0 = __floats2half2_rn(sacc[f0][0], sacc[f0][1]);
                __half2 h1 = __floats2half2_rn(sacc[f0][2], sacc[f0][3]);
                __half2 h2 = __floats2half2_rn(sacc[f1][0], sacc[f1][1]);
                __half2 h3 = __floats2half2_rn(sacc[f1][2], sacc[f1][3]);
                ah2[0] = *reinterpret_cast<uint32_t*>(&h0);
                ah2[1] = *reinterpret_cast<uint32_t*>(&h1);
                ah2[2] = *reinterpret_cast<uint32_t*>(&h2);
                ah2[3] = *reinterpret_cast<uint32_t*>(&h3);
            }
            uint32_t vf[4][4];
#pragma unroll
            for (int nb = 0; nb < 4; nb++) {
                uint32_t off = SWZ((kk * 16 + ((li & 1) << 3) + lj) * 128 + (nb * 16 + ((li >> 1) << 3)) * 2);
                LDSM4T(vf[nb], vst + off);
            }
#pragma unroll
            for (int nb = 0; nb < 4; nb++) { MMA(oacc[2*nb], ah2, vf[nb]); MMA(oacc[2*nb+1], ah2, vf[nb]+2); }
        }

        __syncthreads();
        if (it + 2 < 8) {
            loadKV(it + 2, s);
            asm volatile("cp.async.commit_group;" ::: "memory");
        }
    }

#pragma unroll
    for (int rr = 0; rr < 2; rr++) {
        const int grow = qbase + rbase + rr * 8;
        const float inv = 1.f / l_sum[rr];
        const size_t base = (size_t)(b * CS + grow) * CD + headOff + ((lane & 3) << 1);
#pragma unroll
        for (int ni = 0; ni < 8; ni++) {
            float v0 = oacc[ni][2*rr] * inv, v1 = oacc[ni][2*rr+1] * inv;
            *reinterpret_cast<__half2*>(&Oh[base + 8 * ni]) = __floats2half2_rn(v0, v1);
        }
    }
}

// ---------------------------------------------------------------------------
// mma.sync fp16 GEMM (1-pass, 3-stage pipeline): C[BM x BN] = A . B^T, K=NC*64.
// Warp tile fixed 32x64 (NF=8); warp grid (BM/32) x (BN/64).
// out: fp32 (outf) | fp16 (outh)
// ---------------------------------------------------------------------------
template<int BM, int BN>
__global__ __launch_bounds__((BM/32)*(BN/64)*32)
void mm_gemm(const hf* __restrict__ Ah, int lda,
             const hf* __restrict__ Bh, int ldb,
             float* __restrict__ outf, hf* __restrict__ outh, int ldc,
             const float* __restrict__ bias, const float* __restrict__ res,
             int gelu, int NC)
{
    constexpr int WMC = BM / 32;
    constexpr int WNC = BN / 64;
    constexpr int THREADS = WMC * WNC * 32;
    constexpr int NF  = 8;
    constexpr int ASZ = BM * 128;
    constexpr int BSZ = BN * 128;
    constexpr int STG = ASZ + BSZ;

    extern __shared__ char smem[];
    const uint32_t sb = (uint32_t)__cvta_generic_to_shared(smem);
    const int tid = threadIdx.x, wid = tid >> 5, lane = tid & 31;
    const int bm = blockIdx.y * BM, bn = blockIdx.x * BN;

    const int wm = (wid % WMC) * 32;
    const int wn = (wid / WMC) * 64;

    auto load_chunk = [&](int c, int s) {
        const uint32_t base = sb + s * STG;
        const int k0 = c * 64;
#pragma unroll
        for (int i = 0; i < BM * 8 / THREADS; i++) {
            int u = tid + i * THREADS, r = u >> 3, cu = u & 7;
            CP16(base + SWZ(r * 128 + cu * 16), Ah + (size_t)(bm + r) * lda + k0 + cu * 8);
        }
#pragma unroll
        for (int i = 0; i < BN * 8 / THREADS; i++) {
            int u = tid + i * THREADS, r = u >> 3, cu = u & 7;
            CP16(base + ASZ + SWZ(r * 128 + cu * 16), Bh + (size_t)(bn + r) * ldb + k0 + cu * 8);
        }
    };

    float acc[2][NF][4];
#pragma unroll
    for (int mi = 0; mi < 2; mi++)
#pragma unroll
        for (int ni = 0; ni < NF; ni++)
#pragma unroll
            for (int cc = 0; cc < 4; cc++) acc[mi][ni][cc] = 0.f;

    load_chunk(0, 0);
    asm volatile("cp.async.commit_group;" ::: "memory");
    load_chunk(1, 1);
    asm volatile("cp.async.commit_group;" ::: "memory");

    const int li = lane >> 3, lj = lane & 7;

    for (int c = 0; c < NC; c++) {
        if (c + 2 < NC) {
            load_chunk(c + 2, (c + 2) % 3);
            asm volatile("cp.async.commit_group;" ::: "memory");
            asm volatile("cp.async.wait_group 2;" ::: "memory");
        } else if (c + 1 < NC) {
            asm volatile("cp.async.wait_group 1;" ::: "memory");
        } else {
            asm volatile("cp.async.wait_group 0;" ::: "memory");
        }
        __syncthreads();

        const uint32_t aBase = sb + (c % 3) * STG;
        const uint32_t bBase = aBase + ASZ;

#pragma unroll
        for (int ks = 0; ks < 4; ks++) {
            const int kb = ks * 16;
            uint32_t ah[2][4];
#pragma unroll
            for (int mi = 0; mi < 2; mi++) {
                int row = wm + mi * 16 + ((li & 1) << 3) + lj;
                int col = kb + ((li >> 1) << 3);
                LDSM4(ah[mi], aBase + SWZ(row * 128 + col * 2));
            }
            uint32_t bh[NF][2];
#pragma unroll
            for (int nt = 0; nt < NF / 2; nt++) {
                int row = wn + nt * 16 + ((li >> 1) << 3) + lj;
                int col = kb + ((li & 1) << 3);
                uint32_t r4[4];
                LDSM4(r4, bBase + SWZ(row * 128 + col * 2));
                bh[2*nt][0] = r4[0]; bh[2*nt][1] = r4[1];
                bh[2*nt+1][0] = r4[2]; bh[2*nt+1][1] = r4[3];
            }
#pragma unroll
            for (int mi = 0; mi < 2; mi++)
#pragma unroll
                for (int ni = 0; ni < NF; ni++) MMA(acc[mi][ni], ah[mi], bh[ni]);
        }
        __syncthreads();
    }

#pragma unroll
    for (int mi = 0; mi < 2; mi++) {
#pragma unroll
        for (int ni = 0; ni < NF; ni++) {
            const int m0 = bm + wm + mi * 16 + (lane >> 2);
            const int n0 = bn + wn + ni * 8 + ((lane & 3) << 1);
#pragma unroll
            for (int rr = 0; rr < 2; rr++) {
                const int m = m0 + rr * 8;
                float v0 = acc[mi][ni][2*rr + 0];
                float v1 = acc[mi][ni][2*rr + 1];
                if (bias) { v0 += bias[n0]; v1 += bias[n0 + 1]; }
                if (gelu) { v0 = gelu_f(v0); v1 = gelu_f(v1); }
                size_t idx = (size_t)m * ldc + n0;
                if (res) { v0 += res[idx]; v1 += res[idx + 1]; }
                if (outf) {
                    outf[idx] = v0; outf[idx + 1] = v1;
                } else {
                    *reinterpret_cast<__half2*>(&outh[idx]) = __floats2half2_rn(v0, v1);
                }
            }
        }
    }
}

// ---------------------------------------------------------------------------
extern "C" void kernel_launch(void* const* d_in, const int* in_sizes, int n_in,
                              void* d_out, int out_size)
{
    const float* x    = (const float*)d_in[0];
    const int*   mask = (const int*)  d_in[1];
    const float* wq = (const float*)d_in[2],  *bq = (const float*)d_in[3];
    const float* wk = (const float*)d_in[4],  *bk = (const float*)d_in[5];
    const float* wv = (const float*)d_in[6],  *bv = (const float*)d_in[7];
    const float* wo = (const float*)d_in[8],  *bo = (const float*)d_in[9];
    const float* w1 = (const float*)d_in[10], *b1 = (const float*)d_in[11];
    const float* w2 = (const float*)d_in[12], *b2 = (const float*)d_in[13];
    const float* g1 = (const float*)d_in[14], *be1 = (const float*)d_in[15];
    const float* g2 = (const float*)d_in[16], *be2 = (const float*)d_in[17];
    float* out = (float*)d_out;

    hf *xnh,*qkv,*oh,*h1h,*wqkvc,*woc,*w1c,*w2c;
    float *bqkv;
    cudaGetSymbolAddress((void**)&xnh, g_xnh);
    cudaGetSymbolAddress((void**)&qkv, g_qkv);
    cudaGetSymbolAddress((void**)&oh, g_oh);
    cudaGetSymbolAddress((void**)&h1h, g_h1h);
    cudaGetSymbolAddress((void**)&wqkvc, g_wqkv);
    cudaGetSymbolAddress((void**)&bqkv, g_bqkv);
    cudaGetSymbolAddress((void**)&woc, g_wo);
    cudaGetSymbolAddress((void**)&w1c, g_w1);
    cudaGetSymbolAddress((void**)&w2c, g_w2);

    const int SMBIG = 3 * (128 + 256) * 128;     // 147456, 128x256 3-stage
    const int SMSML = 3 * (64 + 128) * 128;      // 73728,  64x128 3-stage
    const int SMFL  = 16384 + 2 * 32768;         // 81920
    cudaFuncSetAttribute((const void*)mm_gemm<128,256>, cudaFuncAttributeMaxDynamicSharedMemorySize, SMBIG);
    cudaFuncSetAttribute((const void*)mm_gemm<64,128>,  cudaFuncAttributeMaxDynamicSharedMemorySize, SMSML);
    cudaFuncSetAttribute((const void*)flash_kernel, cudaFuncAttributeMaxDynamicSharedMemorySize, SMFL);

    // pack weights: wq*0.125 | wk | wv into g_wqkv; bias packed likewise
    conv_kernel<<<1024, 256>>>(wq, wqkvc,               CD * CD / 4, 0.125f);
    conv_kernel<<<1024, 256>>>(wk, wqkvc + CD * CD,     CD * CD / 4, 1.0f);
    conv_kernel<<<1024, 256>>>(wv, wqkvc + 2 * CD * CD, CD * CD / 4, 1.0f);
    bias_pack_kernel<<<12, 256>>>(bq, bk, bv, bqkv);
    conv_kernel<<<1024, 256>>>(wo, woc, CD * CD / 4, 1.0f);
    conv_kernel<<<4096, 256>>>(w1, w1c, CDFF * CD / 4, 1.0f);
    conv_kernel<<<4096, 256>>>(w2, w2c, CD * CDFF / 4, 1.0f);

    // LN1 -> xn (fp16)
    ln_kernel<<<NTOK, 256>>>(x, g1, be1, xnh);

    // fused QKV projection -> [B,S,3072] (Q pre-scaled by 0.125): 128x256 tiles
    mm_gemm<128,256><<<dim3(CQKV / 256, NTOK / 128), 512, SMBIG>>>(
        xnh, CD, wqkvc, CD, nullptr, qkv, CQKV, bqkv, nullptr, 0, 16);

    // fused attention -> O (fp16)
    dim3 gA(CS / 128, CB * CH);
    flash_kernel<<<gA, 256, SMFL>>>(qkv, mask, oh);

    // x1 = O wo^T + bo + x -> out (fp32): 64x128 tiles (tail-friendly)
    mm_gemm<64,128><<<dim3(CD / 128, NTOK / 64), 128, SMSML>>>(
        oh, CD, woc, CD, out, nullptr, CD, bo, x, 0, 16);

    // LN2 -> xn (fp16)
    ln_kernel<<<NTOK, 256>>>(out, g2, be2, xnh);

    // h1 = gelu(xn w1^T + b1) (fp16): 128x256 tiles
    mm_gemm<128,256><<<dim3(CDFF / 256, NTOK / 128), 512, SMBIG>>>(
        xnh, CD, w1c, CD, nullptr, h1h, CDFF, b1, nullptr, 1, 16);

    // out = x1 + h1 w2^T + b2: 64x128 tiles
    mm_gemm<64,128><<<dim3(CD / 128, NTOK / 64), 128, SMSML>>>(
        h1h, CDFF, w2c, CDFF, out, nullptr, CD, b2, out, 0, 64);
}